// round 14
// baseline (speedup 1.0000x reference)
#include <cuda_runtime.h>
#include <cuda_bf16.h>
#include <cuda_fp16.h>
#include <cstdint>

#define NN 100000
#define EE 1600000
#define FF 602
#define FP 608   // padded K (wc zero-fills 602..607)
#define DEGMAX 64

// ------------------------------------------------------------------
// Scratch (static device globals)
// ------------------------------------------------------------------
__device__ __align__(16) __nv_bfloat16 g_wbT_hi[32 * FP];  // Wc^T hi [n][k]
__device__ __align__(16) __nv_bfloat16 g_wbT_lo[32 * FP];  // Wc^T lo
__device__ float g_bc[32];
__device__ __align__(16) __half g_yh[(size_t)NN * 32];   // y fp16 (gather src)
__device__ __align__(16) __half g_h1h[(size_t)NN * 32];  // h1 fp16 (gather src)
__device__ float g_h2[(size_t)NN * 32];

__device__ int g_cnt[NN];                           // zero at start of replay
__device__ __align__(16) int g_pad[(size_t)NN * DEGMAX];  // padded adj lists

__device__ int g_bins[64];   // degree histogram (zeroed by head each replay)
__device__ int g_bcur[64];   // scan offsets / scatter cursors
__device__ int g_perm[NN];   // nodes sorted by degree

__device__ float g_sum1[32], g_sq1[32];
__device__ float g_sum2[32], g_sq2[32];

// ------------------------------------------------------------------
// small helpers
// ------------------------------------------------------------------
__device__ __forceinline__ float4 f4add(float4 a, float4 b) {
    return make_float4(a.x + b.x, a.y + b.y, a.z + b.z, a.w + b.w);
}

__device__ __forceinline__ float4 ld_h4(const __half* p) {
    uint2 u = *(const uint2*)p;
    __half2 h0 = *(__half2*)&u.x;
    __half2 h1 = *(__half2*)&u.y;
    float2 f0 = __half22float2(h0);
    float2 f1 = __half22float2(h1);
    return make_float4(f0.x, f0.y, f1.x, f1.y);
}

__device__ __forceinline__ void st_h4(__half* p, float4 v) {
    __half2 h0 = __floats2half2_rn(v.x, v.y);
    __half2 h1 = __floats2half2_rn(v.z, v.w);
    uint2 u;
    u.x = *(uint32_t*)&h0;
    u.y = *(uint32_t*)&h1;
    *(uint2*)p = u;
}

// ------------------------------------------------------------------
// place2: one-pass padded-CSR build (g_cnt zero on entry; head re-zeroes)
// ------------------------------------------------------------------
__global__ void __launch_bounds__(256) place2_kernel(const int* __restrict__ ei) {
    const int4* __restrict__ s4 = (const int4*)ei;
    const int4* __restrict__ d4 = (const int4*)(ei + EE);
    const int n4 = EE / 4;
    for (int i = blockIdx.x * 256 + threadIdx.x; i < n4; i += gridDim.x * 256) {
        int4 s = s4[i];
        int4 d = d4[i];
        int p0 = atomicAdd(&g_cnt[d.x], 1);
        int p1 = atomicAdd(&g_cnt[d.y], 1);
        int p2 = atomicAdd(&g_cnt[d.z], 1);
        int p3 = atomicAdd(&g_cnt[d.w], 1);
        g_pad[(size_t)d.x * DEGMAX + p0] = s.x;
        g_pad[(size_t)d.y * DEGMAX + p1] = s.y;
        g_pad[(size_t)d.z * DEGMAX + p2] = s.z;
        g_pad[(size_t)d.w * DEGMAX + p3] = s.w;
    }
}

// ------------------------------------------------------------------
// degree counting sort: histogram -> 64-scan -> scatter
// ------------------------------------------------------------------
__global__ void __launch_bounds__(256) dhist_kernel() {
    int v = blockIdx.x * 256 + threadIdx.x;
    if (v < NN) atomicAdd(&g_bins[g_cnt[v]], 1);
}

__global__ void dscan_kernel() {
    __shared__ int a[64];
    const int t = threadIdx.x;  // 64
    int v = g_bins[t];
    a[t] = v;
    __syncthreads();
    for (int o = 1; o < 64; o <<= 1) {
        int tmp = (t >= o) ? a[t - o] : 0;
        __syncthreads();
        a[t] += tmp;
        __syncthreads();
    }
    g_bcur[t] = a[t] - v;  // exclusive offsets
}

__global__ void __launch_bounds__(256) dscat_kernel() {
    int v = blockIdx.x * 256 + threadIdx.x;
    if (v < NN) {
        int d = g_cnt[v];
        int p = atomicAdd(&g_bcur[d], 1);
        g_perm[p] = v;
    }
}

// ------------------------------------------------------------------
// Wc = lin1_w @ nn1_w1 -> split bf16 transposed; bc; zero BN sums
// ------------------------------------------------------------------
__global__ void __launch_bounds__(256) wc_kernel(
    const float* __restrict__ lw, const float* __restrict__ w1,
    const float* __restrict__ lb) {
    __shared__ float s_w1[64 * 32];
    const int tid = threadIdx.x;
    const int w = tid >> 5, lane = tid & 31;
    for (int i = tid; i < 64 * 32; i += 256) s_w1[i] = w1[i];
    __syncthreads();

    const int f = blockIdx.x * 8 + w;
    if (f < FF) {
        float r0 = lw[f * 64 + lane];
        float r1 = lw[f * 64 + 32 + lane];
        float acc0 = 0.f, acc1 = 0.f;
#pragma unroll
        for (int m = 0; m < 32; m++) {
            float u0 = __shfl_sync(0xffffffffu, r0, m);
            float u1 = __shfl_sync(0xffffffffu, r1, m);
            acc0 = fmaf(u0, s_w1[m * 32 + lane], acc0);
            acc1 = fmaf(u1, s_w1[(m + 32) * 32 + lane], acc1);
        }
        float acc = acc0 + acc1;
        __nv_bfloat16 hi = __float2bfloat16(acc);
        __nv_bfloat16 lo = __float2bfloat16(acc - __bfloat162float(hi));
        g_wbT_hi[lane * FP + f] = hi;
        g_wbT_lo[lane * FP + f] = lo;
    }

    if (blockIdx.x == 0) {
        if (tid < 32 * (FP - FF)) {
            int n = tid / (FP - FF);
            int f2 = FF + tid % (FP - FF);
            g_wbT_hi[n * FP + f2] = __float2bfloat16(0.f);
            g_wbT_lo[n * FP + f2] = __float2bfloat16(0.f);
        }
        if (tid < 32) {
            float acc = 0.f;
#pragma unroll
            for (int m = 0; m < 64; m++)
                acc = fmaf(lb[m], s_w1[m * 32 + tid], acc);
            g_bc[tid] = acc;
            g_sum1[tid] = 0.f;
            g_sq1[tid] = 0.f;
            g_sum2[tid] = 0.f;
            g_sq2[tid] = 0.f;
        }
    }
}

// ------------------------------------------------------------------
// GEMM: split-bf16 HMMA, BM=64, BK=32, 3-stage cp.async; fp16 y store
// ------------------------------------------------------------------
__device__ __forceinline__ void mma_bf16(float* acc, uint32_t a0, uint32_t a1,
                                         uint32_t a2, uint32_t a3, uint32_t b0,
                                         uint32_t b1) {
    asm volatile(
        "mma.sync.aligned.m16n8k16.row.col.f32.bf16.bf16.f32 "
        "{%0,%1,%2,%3}, {%4,%5,%6,%7}, {%8,%9}, {%0,%1,%2,%3};\n"
        : "+f"(acc[0]), "+f"(acc[1]), "+f"(acc[2]), "+f"(acc[3])
        : "r"(a0), "r"(a1), "r"(a2), "r"(a3), "r"(b0), "r"(b1));
}

__device__ __forceinline__ uint2 split2(float2 p) {
    uint32_t h;
    asm("cvt.rn.bf16x2.f32 %0, %1, %2;" : "=r"(h) : "f"(p.y), "f"(p.x));
    float hx = __uint_as_float(h << 16);
    float hy = __uint_as_float(h & 0xffff0000u);
    uint32_t l;
    asm("cvt.rn.bf16x2.f32 %0, %1, %2;" : "=r"(l) : "f"(p.y - hy), "f"(p.x - hx));
    return make_uint2(h, l);
}

#define BM 64
#define AS_WORDS (BM * 40)
#define BS_WORDS (32 * 20)
#define NSTAGE 3
#define NT 19
#define GEMM_SMEM (NSTAGE * (AS_WORDS * 4 + 2 * BS_WORDS * 4))  // 46080

__global__ void __launch_bounds__(256) gemm_kernel(const float* __restrict__ x) {
    extern __shared__ char smem[];
    float* As = (float*)smem;
    uint32_t* Bh = (uint32_t*)(smem + NSTAGE * AS_WORDS * 4);
    uint32_t* Bl = Bh + NSTAGE * BS_WORDS;

    const int tid = threadIdx.x;
    const int wid = tid >> 5, lane = tid & 31;
    const int g = lane >> 2, tig = lane & 3;
    const int mq = wid & 3;
    const int nh = wid >> 2;
    const int row0 = blockIdx.x * BM;

    const uint32_t* __restrict__ wh = (const uint32_t*)g_wbT_hi;
    const uint32_t* __restrict__ wl = (const uint32_t*)g_wbT_lo;

    const uint32_t asb = (uint32_t)__cvta_generic_to_shared(As);
    const uint32_t bhb = (uint32_t)__cvta_generic_to_shared(Bh);
    const uint32_t blb = (uint32_t)__cvta_generic_to_shared(Bl);

    const int b_n = tid >> 3;
    const int b_q = tid & 7;
    const int b_lo = b_q >> 2;
    const int b_c4 = b_q & 3;

    auto load_tile = [&](int t) {
        const int k0 = t * 32;
        const int buf = t % NSTAGE;
#pragma unroll
        for (int it = 0; it < 4; it++) {
            int idx = it * 256 + tid;
            int r = idx >> 4, c2 = idx & 15;
            int grow = row0 + r;
            int k = k0 + c2 * 2;
            const float* src = x + (size_t)grow * FF + k;
            uint32_t dst =
                asb + (uint32_t)(buf * AS_WORDS + r * 40 + c2 * 2) * 4;
            int sz = (grow < NN && k < FF) ? 8 : 0;
            asm volatile("cp.async.ca.shared.global [%0], [%1], 8, %2;\n" ::
                             "r"(dst), "l"(src), "r"(sz));
        }
        {
            const uint32_t* src =
                (b_lo ? wl : wh) + b_n * (FP / 2) + (k0 >> 1) + b_c4 * 4;
            uint32_t dst = (b_lo ? blb : bhb) +
                           (uint32_t)(buf * BS_WORDS + b_n * 20 + b_c4 * 4) * 4;
            asm volatile("cp.async.cg.shared.global [%0], [%1], 16;\n" ::
                             "r"(dst), "l"(src));
        }
        asm volatile("cp.async.commit_group;\n");
    };

    float acc[2][4] = {};

    load_tile(0);
    load_tile(1);

    for (int t = 0; t < NT; t++) {
        if (t < NT - 1) {
            asm volatile("cp.async.wait_group 1;\n");
        } else {
            asm volatile("cp.async.wait_group 0;\n");
        }
        __syncthreads();

        if (t + 2 < NT) load_tile(t + 2);

        const int b = t % NSTAGE;
        const float* A = As + b * AS_WORDS;
        const uint32_t* BH = Bh + b * BS_WORDS;
        const uint32_t* BL = Bl + b * BS_WORDS;

#pragma unroll
        for (int ks = 0; ks < 2; ks++) {
            const int rA = (mq * 16 + g) * 40 + ks * 16 + 2 * tig;
            float2 p0 = *(const float2*)&A[rA];
            float2 p1 = *(const float2*)&A[rA + 8 * 40];
            float2 p2 = *(const float2*)&A[rA + 8];
            float2 p3 = *(const float2*)&A[rA + 8 * 40 + 8];
            uint2 a0 = split2(p0), a1 = split2(p1);
            uint2 a2 = split2(p2), a3 = split2(p3);
#pragma unroll
            for (int nt = 0; nt < 2; nt++) {
                const int rB = (nh * 16 + nt * 8 + g) * 20 + ks * 8 + tig;
                uint32_t b0h = BH[rB];
                uint32_t b1h = BH[rB + 4];
                uint32_t b0l = BL[rB];
                uint32_t b1l = BL[rB + 4];
                mma_bf16(acc[nt], a0.x, a1.x, a2.x, a3.x, b0h, b1h);
                mma_bf16(acc[nt], a0.y, a1.y, a2.y, a3.y, b0h, b1h);
                mma_bf16(acc[nt], a0.x, a1.x, a2.x, a3.x, b0l, b1l);
            }
        }
    }

    const int ra = row0 + mq * 16 + g;
#pragma unroll
    for (int nt = 0; nt < 2; nt++) {
        int col = nh * 16 + nt * 8 + 2 * tig;
        float2 bias = *(const float2*)&g_bc[col];
        if (ra < NN) {
            __half2 h = __floats2half2_rn(acc[nt][0] + bias.x,
                                          acc[nt][1] + bias.y);
            *(__half2*)&g_yh[(size_t)ra * 32 + col] = h;
        }
        if (ra + 8 < NN) {
            __half2 h = __floats2half2_rn(acc[nt][2] + bias.x,
                                          acc[nt][3] + bias.y);
            *(__half2*)&g_yh[(size_t)(ra + 8) * 32 + col] = h;
        }
    }
}

// ------------------------------------------------------------------
// gather4h: padded lists; fp16 rows; int4 index loads; 8 in flight
// ------------------------------------------------------------------
__device__ __forceinline__ float4 gather_row4h(const __half* __restrict__ src,
                                               int v, int r4, int cnt, int mc) {
    const size_t base = (size_t)v * DEGMAX;
    float4 a0 = ld_h4(&src[(size_t)v * 32 + r4]);
    float4 a1 = make_float4(0.f, 0.f, 0.f, 0.f);
    float4 a2 = a1, a3 = a1;
    int i = 0;
    for (; i + 8 <= mc; i += 8) {
        int4 sa = *(const int4*)&g_pad[base + i];
        int4 sb = *(const int4*)&g_pad[base + i + 4];
        float4 t0 = ld_h4(&src[(size_t)sa.x * 32 + r4]);
        float4 t1 = ld_h4(&src[(size_t)sa.y * 32 + r4]);
        float4 t2 = ld_h4(&src[(size_t)sa.z * 32 + r4]);
        float4 t3 = ld_h4(&src[(size_t)sa.w * 32 + r4]);
        float4 t4 = ld_h4(&src[(size_t)sb.x * 32 + r4]);
        float4 t5 = ld_h4(&src[(size_t)sb.y * 32 + r4]);
        float4 t6 = ld_h4(&src[(size_t)sb.z * 32 + r4]);
        float4 t7 = ld_h4(&src[(size_t)sb.w * 32 + r4]);
        if (i < cnt) a0 = f4add(a0, t0);
        if (i + 1 < cnt) a1 = f4add(a1, t1);
        if (i + 2 < cnt) a2 = f4add(a2, t2);
        if (i + 3 < cnt) a3 = f4add(a3, t3);
        if (i + 4 < cnt) a0 = f4add(a0, t4);
        if (i + 5 < cnt) a1 = f4add(a1, t5);
        if (i + 6 < cnt) a2 = f4add(a2, t6);
        if (i + 7 < cnt) a3 = f4add(a3, t7);
    }
    for (; i < mc; i++) {
        int s = g_pad[base + i];
        float4 t = ld_h4(&src[(size_t)s * 32 + r4]);
        if (i < cnt) a0 = f4add(a0, t);
    }
    return f4add(f4add(a0, a1), f4add(a2, a3));
}

// 32x32 matmul in 4-node layout
__device__ __forceinline__ float4 mm32(float T0, float T1, float T2, float T3,
                                       const float* __restrict__ sw,
                                       const float* __restrict__ sb,
                                       int srcbase, int r4) {
    float4 o = *(const float4*)&sb[r4];
#pragma unroll
    for (int kk = 0; kk < 8; kk++) {
        int src = srcbase + kk;
        float u0 = __shfl_sync(0xffffffffu, T0, src);
        float u1 = __shfl_sync(0xffffffffu, T1, src);
        float u2 = __shfl_sync(0xffffffffu, T2, src);
        float u3 = __shfl_sync(0xffffffffu, T3, src);
        float4 w0 = *(const float4*)&sw[(4 * kk) * 32 + r4];
        float4 w1 = *(const float4*)&sw[(4 * kk + 1) * 32 + r4];
        float4 w2 = *(const float4*)&sw[(4 * kk + 2) * 32 + r4];
        float4 w3 = *(const float4*)&sw[(4 * kk + 3) * 32 + r4];
        o.x = fmaf(u0, w0.x, o.x); o.y = fmaf(u0, w0.y, o.y);
        o.z = fmaf(u0, w0.z, o.z); o.w = fmaf(u0, w0.w, o.w);
        o.x = fmaf(u1, w1.x, o.x); o.y = fmaf(u1, w1.y, o.y);
        o.z = fmaf(u1, w1.z, o.z); o.w = fmaf(u1, w1.w, o.w);
        o.x = fmaf(u2, w2.x, o.x); o.y = fmaf(u2, w2.y, o.y);
        o.z = fmaf(u2, w2.z, o.z); o.w = fmaf(u2, w2.w, o.w);
        o.x = fmaf(u3, w3.x, o.x); o.y = fmaf(u3, w3.y, o.y);
        o.z = fmaf(u3, w3.z, o.z); o.w = fmaf(u3, w3.w, o.w);
    }
    return o;
}

#define NCHUNK (NN / 4)  // 25000
#define GSB 592          // 148 SM x 4 blocks: one resident wave

// ------------------------------------------------------------------
// gmlp1: degree-sorted order; a = y[v]+sum_nbr; h1 = relu(a+b1)@w2+b2
// ------------------------------------------------------------------
__global__ void __launch_bounds__(256, 4) gmlp1_kernel(
    const float* __restrict__ b1, const float* __restrict__ w2,
    const float* __restrict__ b2) {
    __shared__ __align__(16) float s_w2[1024];
    __shared__ __align__(16) float s_b1[32], s_b2[32];
    __shared__ float s_red[2][8][32];
    const int tid = threadIdx.x;
    for (int i = tid; i < 1024; i += 256) s_w2[i] = w2[i];
    if (tid < 32) { s_b1[tid] = b1[tid]; s_b2[tid] = b2[tid]; }
    __syncthreads();

    const int w = tid >> 5, lane = tid & 31;
    const int q = lane >> 3, r4 = (lane & 7) * 4;
    const int srcbase = lane & 24;
    float4 b1v = *(const float4*)&s_b1[r4];

    float4 ssum = make_float4(0.f, 0.f, 0.f, 0.f), ssq = ssum;

    for (int c = blockIdx.x * 8 + w; c < NCHUNK; c += GSB * 8) {
        const int v = g_perm[c * 4 + q];
        const int cnt = g_cnt[v];
        int mc = cnt;
        mc = max(mc, __shfl_xor_sync(0xffffffffu, mc, 8));
        mc = max(mc, __shfl_xor_sync(0xffffffffu, mc, 16));

        float4 a = gather_row4h(g_yh, v, r4, cnt, mc);
        float t0 = fmaxf(a.x + b1v.x, 0.f);
        float t1 = fmaxf(a.y + b1v.y, 0.f);
        float t2 = fmaxf(a.z + b1v.z, 0.f);
        float t3 = fmaxf(a.w + b1v.w, 0.f);

        float4 o = mm32(t0, t1, t2, t3, s_w2, s_b2, srcbase, r4);
        st_h4(&g_h1h[(size_t)v * 32 + r4], o);
        ssum = f4add(ssum, o);
        ssq.x = fmaf(o.x, o.x, ssq.x);
        ssq.y = fmaf(o.y, o.y, ssq.y);
        ssq.z = fmaf(o.z, o.z, ssq.z);
        ssq.w = fmaf(o.w, o.w, ssq.w);
    }

#pragma unroll
    for (int m = 8; m <= 16; m <<= 1) {
        ssum.x += __shfl_xor_sync(0xffffffffu, ssum.x, m);
        ssum.y += __shfl_xor_sync(0xffffffffu, ssum.y, m);
        ssum.z += __shfl_xor_sync(0xffffffffu, ssum.z, m);
        ssum.w += __shfl_xor_sync(0xffffffffu, ssum.w, m);
        ssq.x += __shfl_xor_sync(0xffffffffu, ssq.x, m);
        ssq.y += __shfl_xor_sync(0xffffffffu, ssq.y, m);
        ssq.z += __shfl_xor_sync(0xffffffffu, ssq.z, m);
        ssq.w += __shfl_xor_sync(0xffffffffu, ssq.w, m);
    }
    if (lane < 8) {
        *(float4*)&s_red[0][w][r4] = ssum;
        *(float4*)&s_red[1][w][r4] = ssq;
    }
    __syncthreads();
    if (tid < 32) {
        float s = 0.f, qq = 0.f;
#pragma unroll
        for (int ww = 0; ww < 8; ww++) {
            s += s_red[0][ww][tid];
            qq += s_red[1][ww][tid];
        }
        atomicAdd(&g_sum1[tid], s);
        atomicAdd(&g_sq1[tid], qq);
    }
}

// ------------------------------------------------------------------
// gmlp2: degree-sorted; BN1 local; 2 matmuls (+BN2 stats)
// ------------------------------------------------------------------
__global__ void __launch_bounds__(256, 4) gmlp2_kernel(
    const float* __restrict__ w1, const float* __restrict__ b1,
    const float* __restrict__ w2, const float* __restrict__ b2,
    const float* __restrict__ bng, const float* __restrict__ bnb) {
    __shared__ __align__(16) float s_w1[1024], s_w2[1024];
    __shared__ __align__(16) float s_b1[32], s_b2[32];
    __shared__ float s_red[2][8][32];
    const int tid = threadIdx.x;
    for (int i = tid; i < 1024; i += 256) {
        s_w1[i] = w1[i];
        s_w2[i] = w2[i];
    }
    if (tid < 32) { s_b1[tid] = b1[tid]; s_b2[tid] = b2[tid]; }
    __syncthreads();

    const int w = tid >> 5, lane = tid & 31;
    const int q = lane >> 3, r4 = (lane & 7) * 4;
    const int srcbase = lane & 24;

    float4 gs = *(const float4*)&g_sum1[r4];
    float4 gq = *(const float4*)&g_sq1[r4];
    float4 gg = make_float4(bng[r4], bng[r4 + 1], bng[r4 + 2], bng[r4 + 3]);
    float4 gb = make_float4(bnb[r4], bnb[r4 + 1], bnb[r4 + 2], bnb[r4 + 3]);
    float4 sc4, sh4;
    {
        float m0 = gs.x / NN, m1 = gs.y / NN, m2 = gs.z / NN, m3 = gs.w / NN;
        sc4.x = gg.x * rsqrtf(fmaxf(gq.x / NN - m0 * m0, 0.f) + 1e-5f);
        sc4.y = gg.y * rsqrtf(fmaxf(gq.y / NN - m1 * m1, 0.f) + 1e-5f);
        sc4.z = gg.z * rsqrtf(fmaxf(gq.z / NN - m2 * m2, 0.f) + 1e-5f);
        sc4.w = gg.w * rsqrtf(fmaxf(gq.w / NN - m3 * m3, 0.f) + 1e-5f);
        sh4.x = gb.x - m0 * sc4.x;
        sh4.y = gb.y - m1 * sc4.y;
        sh4.z = gb.z - m2 * sc4.z;
        sh4.w = gb.w - m3 * sc4.w;
    }

    float4 ssum = make_float4(0.f, 0.f, 0.f, 0.f), ssq = ssum;

    for (int c = blockIdx.x * 8 + w; c < NCHUNK; c += GSB * 8) {
        const int v = g_perm[c * 4 + q];
        const int cnt = g_cnt[v];
        int mc = cnt;
        mc = max(mc, __shfl_xor_sync(0xffffffffu, mc, 8));
        mc = max(mc, __shfl_xor_sync(0xffffffffu, mc, 16));

        float4 a = gather_row4h(g_h1h, v, r4, cnt, mc);
        float degp1 = (float)(cnt + 1);
        float m0 = fmaf(sc4.x, a.x, degp1 * sh4.x);
        float m1 = fmaf(sc4.y, a.y, degp1 * sh4.y);
        float m2 = fmaf(sc4.z, a.z, degp1 * sh4.z);
        float m3 = fmaf(sc4.w, a.w, degp1 * sh4.w);

        float4 t = mm32(m0, m1, m2, m3, s_w1, s_b1, srcbase, r4);
        t.x = fmaxf(t.x, 0.f);
        t.y = fmaxf(t.y, 0.f);
        t.z = fmaxf(t.z, 0.f);
        t.w = fmaxf(t.w, 0.f);

        float4 o = mm32(t.x, t.y, t.z, t.w, s_w2, s_b2, srcbase, r4);
        *(float4*)&g_h2[(size_t)v * 32 + r4] = o;
        ssum = f4add(ssum, o);
        ssq.x = fmaf(o.x, o.x, ssq.x);
        ssq.y = fmaf(o.y, o.y, ssq.y);
        ssq.z = fmaf(o.z, o.z, ssq.z);
        ssq.w = fmaf(o.w, o.w, ssq.w);
    }

#pragma unroll
    for (int m = 8; m <= 16; m <<= 1) {
        ssum.x += __shfl_xor_sync(0xffffffffu, ssum.x, m);
        ssum.y += __shfl_xor_sync(0xffffffffu, ssum.y, m);
        ssum.z += __shfl_xor_sync(0xffffffffu, ssum.z, m);
        ssum.w += __shfl_xor_sync(0xffffffffu, ssum.w, m);
        ssq.x += __shfl_xor_sync(0xffffffffu, ssq.x, m);
        ssq.y += __shfl_xor_sync(0xffffffffu, ssq.y, m);
        ssq.z += __shfl_xor_sync(0xffffffffu, ssq.z, m);
        ssq.w += __shfl_xor_sync(0xffffffffu, ssq.w, m);
    }
    if (lane < 8) {
        *(float4*)&s_red[0][w][r4] = ssum;
        *(float4*)&s_red[1][w][r4] = ssq;
    }
    __syncthreads();
    if (tid < 32) {
        float s = 0.f, qq = 0.f;
#pragma unroll
        for (int ww = 0; ww < 8; ww++) {
            s += s_red[0][ww][tid];
            qq += s_red[1][ww][tid];
        }
        atomicAdd(&g_sum2[tid], s);
        atomicAdd(&g_sq2[tid], qq);
    }
}

// ------------------------------------------------------------------
// head: natural order; BN2 local; fc1 via mm32; fc2 in 6-col strips.
// Re-zeroes g_cnt and g_bins for the next graph replay.
// ------------------------------------------------------------------
__global__ void __launch_bounds__(256, 4) head_kernel(
    const float* __restrict__ fc1w, const float* __restrict__ fc1b,
    const float* __restrict__ fc2w, const float* __restrict__ fc2b,
    const float* __restrict__ bng, const float* __restrict__ bnb,
    float* __restrict__ out) {
    __shared__ __align__(16) float s_w1[1024];
    __shared__ float s_w2[32 * 41];
    __shared__ __align__(16) float s_b1[32];
    __shared__ float s_b2[48];
    const int tid = threadIdx.x;
    for (int i = tid; i < 1024; i += 256) s_w1[i] = fc1w[i];
    for (int i = tid; i < 32 * 41; i += 256) s_w2[i] = fc2w[i];
    if (tid < 32) s_b1[tid] = fc1b[tid];
    if (tid < 41) s_b2[tid] = fc2b[tid];
    if (tid >= 41 && tid < 48) s_b2[tid] = 0.f;
    if (blockIdx.x == 0 && tid < 64) g_bins[tid] = 0;  // reset histogram
    __syncthreads();

    const int w = tid >> 5, lane = tid & 31;
    const int q = lane >> 3, r = lane & 7, r4 = r * 4;
    const int srcbase = lane & 24;

    float4 gs = *(const float4*)&g_sum2[r4];
    float4 gq = *(const float4*)&g_sq2[r4];
    float4 sc4, sh4;
    {
        float m0 = gs.x / NN, m1 = gs.y / NN, m2 = gs.z / NN, m3 = gs.w / NN;
        sc4.x = bng[r4] * rsqrtf(fmaxf(gq.x / NN - m0 * m0, 0.f) + 1e-5f);
        sc4.y = bng[r4 + 1] * rsqrtf(fmaxf(gq.y / NN - m1 * m1, 0.f) + 1e-5f);
        sc4.z = bng[r4 + 2] * rsqrtf(fmaxf(gq.z / NN - m2 * m2, 0.f) + 1e-5f);
        sc4.w = bng[r4 + 3] * rsqrtf(fmaxf(gq.w / NN - m3 * m3, 0.f) + 1e-5f);
        sh4.x = bnb[r4] - m0 * sc4.x;
        sh4.y = bnb[r4 + 1] - m1 * sc4.y;
        sh4.z = bnb[r4 + 2] - m2 * sc4.z;
        sh4.w = bnb[r4 + 3] - m3 * sc4.w;
    }

    const int c0 = r * 6;
    const int nc = max(0, min(6, 41 - c0));

    for (int c = blockIdx.x * 8 + w; c < NCHUNK; c += GSB * 8) {
        const int v = c * 4 + q;
        if (r == 0) g_cnt[v] = 0;  // reset padded-CSR counters for next replay
        float4 h = *(const float4*)&g_h2[(size_t)v * 32 + r4];
        float x0 = fmaf(sc4.x, h.x, sh4.x);
        float x1 = fmaf(sc4.y, h.y, sh4.y);
        float x2 = fmaf(sc4.z, h.z, sh4.z);
        float x3 = fmaf(sc4.w, h.w, sh4.w);

        float4 t = mm32(x0, x1, x2, x3, s_w1, s_b1, srcbase, r4);
        t.x = fmaxf(t.x, 0.f);
        t.y = fmaxf(t.y, 0.f);
        t.z = fmaxf(t.z, 0.f);
        t.w = fmaxf(t.w, 0.f);

        float o[6];
#pragma unroll
        for (int jj = 0; jj < 6; jj++) o[jj] = s_b2[c0 + jj];

#pragma unroll
        for (int kk = 0; kk < 8; kk++) {
            int src = srcbase + kk;
            float u0 = __shfl_sync(0xffffffffu, t.x, src);
            float u1 = __shfl_sync(0xffffffffu, t.y, src);
            float u2 = __shfl_sync(0xffffffffu, t.z, src);
            float u3 = __shfl_sync(0xffffffffu, t.w, src);
            const float* w0 = &s_w2[(4 * kk) * 41 + c0];
            const float* w1 = &s_w2[(4 * kk + 1) * 41 + c0];
            const float* w2r = &s_w2[(4 * kk + 2) * 41 + c0];
            const float* w3 = &s_w2[(4 * kk + 3) * 41 + c0];
#pragma unroll
            for (int jj = 0; jj < 6; jj++) {
                if (jj < nc) {
                    o[jj] = fmaf(u0, w0[jj], o[jj]);
                    o[jj] = fmaf(u1, w1[jj], o[jj]);
                    o[jj] = fmaf(u2, w2r[jj], o[jj]);
                    o[jj] = fmaf(u3, w3[jj], o[jj]);
                }
            }
        }
#pragma unroll
        for (int jj = 0; jj < 6; jj++)
            if (jj < nc) out[(size_t)v * 41 + c0 + jj] = o[jj];
    }
}

// ------------------------------------------------------------------
// launch: gemm in ncu slot #4; sort kernels interleaved on side stream
// ------------------------------------------------------------------
static cudaStream_t g_side = nullptr;
static cudaEvent_t g_evFork = nullptr, g_evJoin = nullptr;

extern "C" void kernel_launch(void* const* d_in, const int* in_sizes, int n_in,
                              void* d_out, int out_size) {
    const float* x = (const float*)d_in[0];
    const int* ei = (const int*)d_in[1];
    const float* lin1_w = (const float*)d_in[2];
    const float* lin1_b = (const float*)d_in[3];
    const float* nn1_w1 = (const float*)d_in[4];
    const float* nn1_b1 = (const float*)d_in[5];
    const float* nn1_w2 = (const float*)d_in[6];
    const float* nn1_b2 = (const float*)d_in[7];
    const float* bn1_g = (const float*)d_in[8];
    const float* bn1_b = (const float*)d_in[9];
    const float* nn2_w1 = (const float*)d_in[10];
    const float* nn2_b1 = (const float*)d_in[11];
    const float* nn2_w2 = (const float*)d_in[12];
    const float* nn2_b2 = (const float*)d_in[13];
    const float* bn2_g = (const float*)d_in[14];
    const float* bn2_b = (const float*)d_in[15];
    const float* fc1_w = (const float*)d_in[16];
    const float* fc1_b = (const float*)d_in[17];
    const float* fc2_w = (const float*)d_in[18];
    const float* fc2_b = (const float*)d_in[19];
    float* out = (float*)d_out;

    if (!g_side) {
        int lo, hi;
        cudaDeviceGetStreamPriorityRange(&lo, &hi);
        cudaStreamCreateWithPriority(&g_side, cudaStreamNonBlocking, hi);
        cudaEventCreateWithFlags(&g_evFork, cudaEventDisableTiming);
        cudaEventCreateWithFlags(&g_evJoin, cudaEventDisableTiming);
        cudaFuncSetAttribute(gemm_kernel,
                             cudaFuncAttributeMaxDynamicSharedMemorySize,
                             GEMM_SMEM);
    }

    cudaEventRecord(g_evFork, 0);
    cudaStreamWaitEvent(g_side, g_evFork, 0);

    place2_kernel<<<256, 256, 0, g_side>>>(ei);                       // #1
    dhist_kernel<<<(NN + 255) / 256, 256, 0, g_side>>>();             // #2
    wc_kernel<<<(FF + 7) / 8, 256>>>(lin1_w, nn1_w1, lin1_b);         // #3
    gemm_kernel<<<(NN + BM - 1) / BM, 256, GEMM_SMEM>>>(x);           // #4 (profiled)
    dscan_kernel<<<1, 64, 0, g_side>>>();                             // #5
    dscat_kernel<<<(NN + 255) / 256, 256, 0, g_side>>>();             // #6

    cudaEventRecord(g_evJoin, g_side);
    cudaStreamWaitEvent(0, g_evJoin, 0);

    gmlp1_kernel<<<GSB, 256>>>(nn1_b1, nn1_w2, nn1_b2);               // #7
    gmlp2_kernel<<<GSB, 256>>>(nn2_w1, nn2_b1, nn2_w2, nn2_b2, bn1_g, bn1_b);
    head_kernel<<<GSB, 256>>>(fc1_w, fc1_b, fc2_w, fc2_b, bn2_g, bn2_b, out);
}

// round 15
// speedup vs baseline: 1.0820x; 1.0820x over previous
#include <cuda_runtime.h>
#include <cuda_bf16.h>
#include <cuda_fp16.h>
#include <cstdint>

#define NN 100000
#define EE 1600000
#define FF 602
#define FP 608   // padded K (wc zero-fills 602..607)
#define DEGMAX 64

// ------------------------------------------------------------------
// Scratch (static device globals)
// ------------------------------------------------------------------
__device__ __align__(16) __nv_bfloat16 g_wbT_hi[32 * FP];  // Wc^T hi [n][k]
__device__ __align__(16) __nv_bfloat16 g_wbT_lo[32 * FP];  // Wc^T lo
__device__ float g_bc[32];
// +1 sentinel row (node NN): statically zero, never written
__device__ __align__(16) __half g_yh[(size_t)(NN + 1) * 32];
__device__ __align__(16) __half g_h1h[(size_t)(NN + 1) * 32];
__device__ float g_h2[(size_t)NN * 32];

__device__ int g_cnt[NN];                           // zero at start of replay
__device__ __align__(16) int g_pad[(size_t)NN * DEGMAX];  // padded adj lists

__device__ float g_sum1[32], g_sq1[32];
__device__ float g_sum2[32], g_sq2[32];

// ------------------------------------------------------------------
// small helpers
// ------------------------------------------------------------------
__device__ __forceinline__ float4 f4add(float4 a, float4 b) {
    return make_float4(a.x + b.x, a.y + b.y, a.z + b.z, a.w + b.w);
}

__device__ __forceinline__ float4 ld_h4(const __half* p) {
    uint2 u = *(const uint2*)p;
    __half2 h0 = *(__half2*)&u.x;
    __half2 h1 = *(__half2*)&u.y;
    float2 f0 = __half22float2(h0);
    float2 f1 = __half22float2(h1);
    return make_float4(f0.x, f0.y, f1.x, f1.y);
}

__device__ __forceinline__ void st_h4(__half* p, float4 v) {
    __half2 h0 = __floats2half2_rn(v.x, v.y);
    __half2 h1 = __floats2half2_rn(v.z, v.w);
    uint2 u;
    u.x = *(uint32_t*)&h0;
    u.y = *(uint32_t*)&h1;
    *(uint2*)p = u;
}

// ------------------------------------------------------------------
// place2: one-pass padded-CSR build (g_cnt zero on entry; head re-zeroes)
// ------------------------------------------------------------------
__global__ void __launch_bounds__(256) place2_kernel(const int* __restrict__ ei) {
    const int4* __restrict__ s4 = (const int4*)ei;
    const int4* __restrict__ d4 = (const int4*)(ei + EE);
    const int n4 = EE / 4;
    for (int i = blockIdx.x * 256 + threadIdx.x; i < n4; i += gridDim.x * 256) {
        int4 s = s4[i];
        int4 d = d4[i];
        int p0 = atomicAdd(&g_cnt[d.x], 1);
        int p1 = atomicAdd(&g_cnt[d.y], 1);
        int p2 = atomicAdd(&g_cnt[d.z], 1);
        int p3 = atomicAdd(&g_cnt[d.w], 1);
        g_pad[(size_t)d.x * DEGMAX + p0] = s.x;
        g_pad[(size_t)d.y * DEGMAX + p1] = s.y;
        g_pad[(size_t)d.z * DEGMAX + p2] = s.z;
        g_pad[(size_t)d.w * DEGMAX + p3] = s.w;
    }
}

// ------------------------------------------------------------------
// padfill: fill pad slots [cnt, align8(group max)) with sentinel NN
// (sentinel row is zero -> gathers need no predicates, no remainder)
// ------------------------------------------------------------------
__global__ void __launch_bounds__(256) padfill_kernel() {
    int v = blockIdx.x * 256 + threadIdx.x;
    if (v < NN) {
        int gbase = v & ~3;  // warp-group of 4 nodes in gather kernels
        int m = g_cnt[gbase];
        m = max(m, g_cnt[gbase + 1]);
        m = max(m, g_cnt[gbase + 2]);
        m = max(m, g_cnt[gbase + 3]);
        int mcr = min((m + 7) & ~7, DEGMAX);
        int c = g_cnt[v];
        for (int i = c; i < mcr; i++) g_pad[(size_t)v * DEGMAX + i] = NN;
    }
}

// ------------------------------------------------------------------
// Wc = lin1_w @ nn1_w1 -> split bf16 transposed; bc; zero BN sums
// ------------------------------------------------------------------
__global__ void __launch_bounds__(256) wc_kernel(
    const float* __restrict__ lw, const float* __restrict__ w1,
    const float* __restrict__ lb) {
    __shared__ float s_w1[64 * 32];
    const int tid = threadIdx.x;
    const int w = tid >> 5, lane = tid & 31;
    for (int i = tid; i < 64 * 32; i += 256) s_w1[i] = w1[i];
    __syncthreads();

    const int f = blockIdx.x * 8 + w;
    if (f < FF) {
        float r0 = lw[f * 64 + lane];
        float r1 = lw[f * 64 + 32 + lane];
        float acc0 = 0.f, acc1 = 0.f;
#pragma unroll
        for (int m = 0; m < 32; m++) {
            float u0 = __shfl_sync(0xffffffffu, r0, m);
            float u1 = __shfl_sync(0xffffffffu, r1, m);
            acc0 = fmaf(u0, s_w1[m * 32 + lane], acc0);
            acc1 = fmaf(u1, s_w1[(m + 32) * 32 + lane], acc1);
        }
        float acc = acc0 + acc1;
        __nv_bfloat16 hi = __float2bfloat16(acc);
        __nv_bfloat16 lo = __float2bfloat16(acc - __bfloat162float(hi));
        g_wbT_hi[lane * FP + f] = hi;
        g_wbT_lo[lane * FP + f] = lo;
    }

    if (blockIdx.x == 0) {
        if (tid < 32 * (FP - FF)) {
            int n = tid / (FP - FF);
            int f2 = FF + tid % (FP - FF);
            g_wbT_hi[n * FP + f2] = __float2bfloat16(0.f);
            g_wbT_lo[n * FP + f2] = __float2bfloat16(0.f);
        }
        if (tid < 32) {
            float acc = 0.f;
#pragma unroll
            for (int m = 0; m < 64; m++)
                acc = fmaf(lb[m], s_w1[m * 32 + tid], acc);
            g_bc[tid] = acc;
            g_sum1[tid] = 0.f;
            g_sq1[tid] = 0.f;
            g_sum2[tid] = 0.f;
            g_sq2[tid] = 0.f;
        }
    }
}

// ------------------------------------------------------------------
// GEMM: split-bf16 HMMA, BM=64, BK=32, 3-stage cp.async; fp16 y store
// ------------------------------------------------------------------
__device__ __forceinline__ void mma_bf16(float* acc, uint32_t a0, uint32_t a1,
                                         uint32_t a2, uint32_t a3, uint32_t b0,
                                         uint32_t b1) {
    asm volatile(
        "mma.sync.aligned.m16n8k16.row.col.f32.bf16.bf16.f32 "
        "{%0,%1,%2,%3}, {%4,%5,%6,%7}, {%8,%9}, {%0,%1,%2,%3};\n"
        : "+f"(acc[0]), "+f"(acc[1]), "+f"(acc[2]), "+f"(acc[3])
        : "r"(a0), "r"(a1), "r"(a2), "r"(a3), "r"(b0), "r"(b1));
}

__device__ __forceinline__ uint2 split2(float2 p) {
    uint32_t h;
    asm("cvt.rn.bf16x2.f32 %0, %1, %2;" : "=r"(h) : "f"(p.y), "f"(p.x));
    float hx = __uint_as_float(h << 16);
    float hy = __uint_as_float(h & 0xffff0000u);
    uint32_t l;
    asm("cvt.rn.bf16x2.f32 %0, %1, %2;" : "=r"(l) : "f"(p.y - hy), "f"(p.x - hx));
    return make_uint2(h, l);
}

#define BM 64
#define AS_WORDS (BM * 40)
#define BS_WORDS (32 * 20)
#define NSTAGE 3
#define NT 19
#define GEMM_SMEM (NSTAGE * (AS_WORDS * 4 + 2 * BS_WORDS * 4))  // 46080

__global__ void __launch_bounds__(256) gemm_kernel(const float* __restrict__ x) {
    extern __shared__ char smem[];
    float* As = (float*)smem;
    uint32_t* Bh = (uint32_t*)(smem + NSTAGE * AS_WORDS * 4);
    uint32_t* Bl = Bh + NSTAGE * BS_WORDS;

    const int tid = threadIdx.x;
    const int wid = tid >> 5, lane = tid & 31;
    const int g = lane >> 2, tig = lane & 3;
    const int mq = wid & 3;
    const int nh = wid >> 2;
    const int row0 = blockIdx.x * BM;

    const uint32_t* __restrict__ wh = (const uint32_t*)g_wbT_hi;
    const uint32_t* __restrict__ wl = (const uint32_t*)g_wbT_lo;

    const uint32_t asb = (uint32_t)__cvta_generic_to_shared(As);
    const uint32_t bhb = (uint32_t)__cvta_generic_to_shared(Bh);
    const uint32_t blb = (uint32_t)__cvta_generic_to_shared(Bl);

    const int b_n = tid >> 3;
    const int b_q = tid & 7;
    const int b_lo = b_q >> 2;
    const int b_c4 = b_q & 3;

    auto load_tile = [&](int t) {
        const int k0 = t * 32;
        const int buf = t % NSTAGE;
#pragma unroll
        for (int it = 0; it < 4; it++) {
            int idx = it * 256 + tid;
            int r = idx >> 4, c2 = idx & 15;
            int grow = row0 + r;
            int k = k0 + c2 * 2;
            const float* src = x + (size_t)grow * FF + k;
            uint32_t dst =
                asb + (uint32_t)(buf * AS_WORDS + r * 40 + c2 * 2) * 4;
            int sz = (grow < NN && k < FF) ? 8 : 0;
            asm volatile("cp.async.ca.shared.global [%0], [%1], 8, %2;\n" ::
                             "r"(dst), "l"(src), "r"(sz));
        }
        {
            const uint32_t* src =
                (b_lo ? wl : wh) + b_n * (FP / 2) + (k0 >> 1) + b_c4 * 4;
            uint32_t dst = (b_lo ? blb : bhb) +
                           (uint32_t)(buf * BS_WORDS + b_n * 20 + b_c4 * 4) * 4;
            asm volatile("cp.async.cg.shared.global [%0], [%1], 16;\n" ::
                             "r"(dst), "l"(src));
        }
        asm volatile("cp.async.commit_group;\n");
    };

    float acc[2][4] = {};

    load_tile(0);
    load_tile(1);

    for (int t = 0; t < NT; t++) {
        if (t < NT - 1) {
            asm volatile("cp.async.wait_group 1;\n");
        } else {
            asm volatile("cp.async.wait_group 0;\n");
        }
        __syncthreads();

        if (t + 2 < NT) load_tile(t + 2);

        const int b = t % NSTAGE;
        const float* A = As + b * AS_WORDS;
        const uint32_t* BH = Bh + b * BS_WORDS;
        const uint32_t* BL = Bl + b * BS_WORDS;

#pragma unroll
        for (int ks = 0; ks < 2; ks++) {
            const int rA = (mq * 16 + g) * 40 + ks * 16 + 2 * tig;
            float2 p0 = *(const float2*)&A[rA];
            float2 p1 = *(const float2*)&A[rA + 8 * 40];
            float2 p2 = *(const float2*)&A[rA + 8];
            float2 p3 = *(const float2*)&A[rA + 8 * 40 + 8];
            uint2 a0 = split2(p0), a1 = split2(p1);
            uint2 a2 = split2(p2), a3 = split2(p3);
#pragma unroll
            for (int nt = 0; nt < 2; nt++) {
                const int rB = (nh * 16 + nt * 8 + g) * 20 + ks * 8 + tig;
                uint32_t b0h = BH[rB];
                uint32_t b1h = BH[rB + 4];
                uint32_t b0l = BL[rB];
                uint32_t b1l = BL[rB + 4];
                mma_bf16(acc[nt], a0.x, a1.x, a2.x, a3.x, b0h, b1h);
                mma_bf16(acc[nt], a0.y, a1.y, a2.y, a3.y, b0h, b1h);
                mma_bf16(acc[nt], a0.x, a1.x, a2.x, a3.x, b0l, b1l);
            }
        }
    }

    const int ra = row0 + mq * 16 + g;
#pragma unroll
    for (int nt = 0; nt < 2; nt++) {
        int col = nh * 16 + nt * 8 + 2 * tig;
        float2 bias = *(const float2*)&g_bc[col];
        if (ra < NN) {
            __half2 h = __floats2half2_rn(acc[nt][0] + bias.x,
                                          acc[nt][1] + bias.y);
            *(__half2*)&g_yh[(size_t)ra * 32 + col] = h;
        }
        if (ra + 8 < NN) {
            __half2 h = __floats2half2_rn(acc[nt][2] + bias.x,
                                          acc[nt][3] + bias.y);
            *(__half2*)&g_yh[(size_t)(ra + 8) * 32 + col] = h;
        }
    }
}

// ------------------------------------------------------------------
// gather4h: predicate-free (sentinel-padded lists); 8 rows in flight
// mcr must be a multiple of 8 covering all 4 warp-nodes' degrees
// ------------------------------------------------------------------
__device__ __forceinline__ float4 gather_row4h(const __half* __restrict__ src,
                                               int v, int r4, int mcr) {
    const size_t base = (size_t)v * DEGMAX;
    float4 a0 = ld_h4(&src[(size_t)v * 32 + r4]);
    float4 a1 = make_float4(0.f, 0.f, 0.f, 0.f);
    float4 a2 = a1, a3 = a1;
    for (int i = 0; i < mcr; i += 8) {
        int4 sa = *(const int4*)&g_pad[base + i];
        int4 sb = *(const int4*)&g_pad[base + i + 4];
        a0 = f4add(a0, ld_h4(&src[(size_t)sa.x * 32 + r4]));
        a1 = f4add(a1, ld_h4(&src[(size_t)sa.y * 32 + r4]));
        a2 = f4add(a2, ld_h4(&src[(size_t)sa.z * 32 + r4]));
        a3 = f4add(a3, ld_h4(&src[(size_t)sa.w * 32 + r4]));
        a0 = f4add(a0, ld_h4(&src[(size_t)sb.x * 32 + r4]));
        a1 = f4add(a1, ld_h4(&src[(size_t)sb.y * 32 + r4]));
        a2 = f4add(a2, ld_h4(&src[(size_t)sb.z * 32 + r4]));
        a3 = f4add(a3, ld_h4(&src[(size_t)sb.w * 32 + r4]));
    }
    return f4add(f4add(a0, a1), f4add(a2, a3));
}

// 32x32 matmul in 4-node layout
__device__ __forceinline__ float4 mm32(float T0, float T1, float T2, float T3,
                                       const float* __restrict__ sw,
                                       const float* __restrict__ sb,
                                       int srcbase, int r4) {
    float4 o = *(const float4*)&sb[r4];
#pragma unroll
    for (int kk = 0; kk < 8; kk++) {
        int src = srcbase + kk;
        float u0 = __shfl_sync(0xffffffffu, T0, src);
        float u1 = __shfl_sync(0xffffffffu, T1, src);
        float u2 = __shfl_sync(0xffffffffu, T2, src);
        float u3 = __shfl_sync(0xffffffffu, T3, src);
        float4 w0 = *(const float4*)&sw[(4 * kk) * 32 + r4];
        float4 w1 = *(const float4*)&sw[(4 * kk + 1) * 32 + r4];
        float4 w2 = *(const float4*)&sw[(4 * kk + 2) * 32 + r4];
        float4 w3 = *(const float4*)&sw[(4 * kk + 3) * 32 + r4];
        o.x = fmaf(u0, w0.x, o.x); o.y = fmaf(u0, w0.y, o.y);
        o.z = fmaf(u0, w0.z, o.z); o.w = fmaf(u0, w0.w, o.w);
        o.x = fmaf(u1, w1.x, o.x); o.y = fmaf(u1, w1.y, o.y);
        o.z = fmaf(u1, w1.z, o.z); o.w = fmaf(u1, w1.w, o.w);
        o.x = fmaf(u2, w2.x, o.x); o.y = fmaf(u2, w2.y, o.y);
        o.z = fmaf(u2, w2.z, o.z); o.w = fmaf(u2, w2.w, o.w);
        o.x = fmaf(u3, w3.x, o.x); o.y = fmaf(u3, w3.y, o.y);
        o.z = fmaf(u3, w3.z, o.z); o.w = fmaf(u3, w3.w, o.w);
    }
    return o;
}

#define NCHUNK (NN / 4)  // 25000
#define GSB 592          // 148 SM x 4 blocks: one resident wave

// ------------------------------------------------------------------
// gmlp1: a = y[v]+sum_nbr (fp16 src); t = relu(a+b1); h1 = t@w2+b2
// ------------------------------------------------------------------
__global__ void __launch_bounds__(256, 4) gmlp1_kernel(
    const float* __restrict__ b1, const float* __restrict__ w2,
    const float* __restrict__ b2) {
    __shared__ __align__(16) float s_w2[1024];
    __shared__ __align__(16) float s_b1[32], s_b2[32];
    __shared__ float s_red[2][8][32];
    const int tid = threadIdx.x;
    for (int i = tid; i < 1024; i += 256) s_w2[i] = w2[i];
    if (tid < 32) { s_b1[tid] = b1[tid]; s_b2[tid] = b2[tid]; }
    __syncthreads();

    const int w = tid >> 5, lane = tid & 31;
    const int q = lane >> 3, r4 = (lane & 7) * 4;
    const int srcbase = lane & 24;
    float4 b1v = *(const float4*)&s_b1[r4];

    float4 ssum = make_float4(0.f, 0.f, 0.f, 0.f), ssq = ssum;

    for (int c = blockIdx.x * 8 + w; c < NCHUNK; c += GSB * 8) {
        const int v = c * 4 + q;
        int mc = g_cnt[v];
        mc = max(mc, __shfl_xor_sync(0xffffffffu, mc, 8));
        mc = max(mc, __shfl_xor_sync(0xffffffffu, mc, 16));
        const int mcr = min((mc + 7) & ~7, DEGMAX);

        float4 a = gather_row4h(g_yh, v, r4, mcr);
        float t0 = fmaxf(a.x + b1v.x, 0.f);
        float t1 = fmaxf(a.y + b1v.y, 0.f);
        float t2 = fmaxf(a.z + b1v.z, 0.f);
        float t3 = fmaxf(a.w + b1v.w, 0.f);

        float4 o = mm32(t0, t1, t2, t3, s_w2, s_b2, srcbase, r4);
        st_h4(&g_h1h[(size_t)v * 32 + r4], o);
        ssum = f4add(ssum, o);
        ssq.x = fmaf(o.x, o.x, ssq.x);
        ssq.y = fmaf(o.y, o.y, ssq.y);
        ssq.z = fmaf(o.z, o.z, ssq.z);
        ssq.w = fmaf(o.w, o.w, ssq.w);
    }

#pragma unroll
    for (int m = 8; m <= 16; m <<= 1) {
        ssum.x += __shfl_xor_sync(0xffffffffu, ssum.x, m);
        ssum.y += __shfl_xor_sync(0xffffffffu, ssum.y, m);
        ssum.z += __shfl_xor_sync(0xffffffffu, ssum.z, m);
        ssum.w += __shfl_xor_sync(0xffffffffu, ssum.w, m);
        ssq.x += __shfl_xor_sync(0xffffffffu, ssq.x, m);
        ssq.y += __shfl_xor_sync(0xffffffffu, ssq.y, m);
        ssq.z += __shfl_xor_sync(0xffffffffu, ssq.z, m);
        ssq.w += __shfl_xor_sync(0xffffffffu, ssq.w, m);
    }
    if (lane < 8) {
        *(float4*)&s_red[0][w][r4] = ssum;
        *(float4*)&s_red[1][w][r4] = ssq;
    }
    __syncthreads();
    if (tid < 32) {
        float s = 0.f, qq = 0.f;
#pragma unroll
        for (int ww = 0; ww < 8; ww++) {
            s += s_red[0][ww][tid];
            qq += s_red[1][ww][tid];
        }
        atomicAdd(&g_sum1[tid], s);
        atomicAdd(&g_sq1[tid], qq);
    }
}

// ------------------------------------------------------------------
// gmlp2: BN1 local; m = sc*(h1[v]+sum)+(deg+1)*sh; 2 matmuls (+BN2 stats)
// ------------------------------------------------------------------
__global__ void __launch_bounds__(256, 4) gmlp2_kernel(
    const float* __restrict__ w1, const float* __restrict__ b1,
    const float* __restrict__ w2, const float* __restrict__ b2,
    const float* __restrict__ bng, const float* __restrict__ bnb) {
    __shared__ __align__(16) float s_w1[1024], s_w2[1024];
    __shared__ __align__(16) float s_b1[32], s_b2[32];
    __shared__ float s_red[2][8][32];
    const int tid = threadIdx.x;
    for (int i = tid; i < 1024; i += 256) {
        s_w1[i] = w1[i];
        s_w2[i] = w2[i];
    }
    if (tid < 32) { s_b1[tid] = b1[tid]; s_b2[tid] = b2[tid]; }
    __syncthreads();

    const int w = tid >> 5, lane = tid & 31;
    const int q = lane >> 3, r4 = (lane & 7) * 4;
    const int srcbase = lane & 24;

    float4 gs = *(const float4*)&g_sum1[r4];
    float4 gq = *(const float4*)&g_sq1[r4];
    float4 gg = make_float4(bng[r4], bng[r4 + 1], bng[r4 + 2], bng[r4 + 3]);
    float4 gb = make_float4(bnb[r4], bnb[r4 + 1], bnb[r4 + 2], bnb[r4 + 3]);
    float4 sc4, sh4;
    {
        float m0 = gs.x / NN, m1 = gs.y / NN, m2 = gs.z / NN, m3 = gs.w / NN;
        sc4.x = gg.x * rsqrtf(fmaxf(gq.x / NN - m0 * m0, 0.f) + 1e-5f);
        sc4.y = gg.y * rsqrtf(fmaxf(gq.y / NN - m1 * m1, 0.f) + 1e-5f);
        sc4.z = gg.z * rsqrtf(fmaxf(gq.z / NN - m2 * m2, 0.f) + 1e-5f);
        sc4.w = gg.w * rsqrtf(fmaxf(gq.w / NN - m3 * m3, 0.f) + 1e-5f);
        sh4.x = gb.x - m0 * sc4.x;
        sh4.y = gb.y - m1 * sc4.y;
        sh4.z = gb.z - m2 * sc4.z;
        sh4.w = gb.w - m3 * sc4.w;
    }

    float4 ssum = make_float4(0.f, 0.f, 0.f, 0.f), ssq = ssum;

    for (int c = blockIdx.x * 8 + w; c < NCHUNK; c += GSB * 8) {
        const int v = c * 4 + q;
        const int cnt = g_cnt[v];
        int mc = cnt;
        mc = max(mc, __shfl_xor_sync(0xffffffffu, mc, 8));
        mc = max(mc, __shfl_xor_sync(0xffffffffu, mc, 16));
        const int mcr = min((mc + 7) & ~7, DEGMAX);

        float4 a = gather_row4h(g_h1h, v, r4, mcr);
        float degp1 = (float)(cnt + 1);
        float m0 = fmaf(sc4.x, a.x, degp1 * sh4.x);
        float m1 = fmaf(sc4.y, a.y, degp1 * sh4.y);
        float m2 = fmaf(sc4.z, a.z, degp1 * sh4.z);
        float m3 = fmaf(sc4.w, a.w, degp1 * sh4.w);

        float4 t = mm32(m0, m1, m2, m3, s_w1, s_b1, srcbase, r4);
        t.x = fmaxf(t.x, 0.f);
        t.y = fmaxf(t.y, 0.f);
        t.z = fmaxf(t.z, 0.f);
        t.w = fmaxf(t.w, 0.f);

        float4 o = mm32(t.x, t.y, t.z, t.w, s_w2, s_b2, srcbase, r4);
        *(float4*)&g_h2[(size_t)v * 32 + r4] = o;
        ssum = f4add(ssum, o);
        ssq.x = fmaf(o.x, o.x, ssq.x);
        ssq.y = fmaf(o.y, o.y, ssq.y);
        ssq.z = fmaf(o.z, o.z, ssq.z);
        ssq.w = fmaf(o.w, o.w, ssq.w);
    }

#pragma unroll
    for (int m = 8; m <= 16; m <<= 1) {
        ssum.x += __shfl_xor_sync(0xffffffffu, ssum.x, m);
        ssum.y += __shfl_xor_sync(0xffffffffu, ssum.y, m);
        ssum.z += __shfl_xor_sync(0xffffffffu, ssum.z, m);
        ssum.w += __shfl_xor_sync(0xffffffffu, ssum.w, m);
        ssq.x += __shfl_xor_sync(0xffffffffu, ssq.x, m);
        ssq.y += __shfl_xor_sync(0xffffffffu, ssq.y, m);
        ssq.z += __shfl_xor_sync(0xffffffffu, ssq.z, m);
        ssq.w += __shfl_xor_sync(0xffffffffu, ssq.w, m);
    }
    if (lane < 8) {
        *(float4*)&s_red[0][w][r4] = ssum;
        *(float4*)&s_red[1][w][r4] = ssq;
    }
    __syncthreads();
    if (tid < 32) {
        float s = 0.f, qq = 0.f;
#pragma unroll
        for (int ww = 0; ww < 8; ww++) {
            s += s_red[0][ww][tid];
            qq += s_red[1][ww][tid];
        }
        atomicAdd(&g_sum2[tid], s);
        atomicAdd(&g_sq2[tid], qq);
    }
}

// ------------------------------------------------------------------
// head: 4-node layout; BN2 local; fc1 via mm32; fc2 in 6-col strips.
// Re-zeroes g_cnt for the next graph replay.
// ------------------------------------------------------------------
__global__ void __launch_bounds__(256, 4) head_kernel(
    const float* __restrict__ fc1w, const float* __restrict__ fc1b,
    const float* __restrict__ fc2w, const float* __restrict__ fc2b,
    const float* __restrict__ bng, const float* __restrict__ bnb,
    float* __restrict__ out) {
    __shared__ __align__(16) float s_w1[1024];
    __shared__ float s_w2[32 * 41];
    __shared__ __align__(16) float s_b1[32];
    __shared__ float s_b2[48];
    const int tid = threadIdx.x;
    for (int i = tid; i < 1024; i += 256) s_w1[i] = fc1w[i];
    for (int i = tid; i < 32 * 41; i += 256) s_w2[i] = fc2w[i];
    if (tid < 32) s_b1[tid] = fc1b[tid];
    if (tid < 41) s_b2[tid] = fc2b[tid];
    if (tid >= 41 && tid < 48) s_b2[tid] = 0.f;
    __syncthreads();

    const int w = tid >> 5, lane = tid & 31;
    const int q = lane >> 3, r = lane & 7, r4 = r * 4;
    const int srcbase = lane & 24;

    float4 gs = *(const float4*)&g_sum2[r4];
    float4 gq = *(const float4*)&g_sq2[r4];
    float4 sc4, sh4;
    {
        float m0 = gs.x / NN, m1 = gs.y / NN, m2 = gs.z / NN, m3 = gs.w / NN;
        sc4.x = bng[r4] * rsqrtf(fmaxf(gq.x / NN - m0 * m0, 0.f) + 1e-5f);
        sc4.y = bng[r4 + 1] * rsqrtf(fmaxf(gq.y / NN - m1 * m1, 0.f) + 1e-5f);
        sc4.z = bng[r4 + 2] * rsqrtf(fmaxf(gq.z / NN - m2 * m2, 0.f) + 1e-5f);
        sc4.w = bng[r4 + 3] * rsqrtf(fmaxf(gq.w / NN - m3 * m3, 0.f) + 1e-5f);
        sh4.x = bnb[r4] - m0 * sc4.x;
        sh4.y = bnb[r4 + 1] - m1 * sc4.y;
        sh4.z = bnb[r4 + 2] - m2 * sc4.z;
        sh4.w = bnb[r4 + 3] - m3 * sc4.w;
    }

    const int c0 = r * 6;
    const int nc = max(0, min(6, 41 - c0));

    for (int c = blockIdx.x * 8 + w; c < NCHUNK; c += GSB * 8) {
        const int v = c * 4 + q;
        if (r == 0) g_cnt[v] = 0;  // reset padded-CSR counters for next replay
        float4 h = *(const float4*)&g_h2[(size_t)v * 32 + r4];
        float x0 = fmaf(sc4.x, h.x, sh4.x);
        float x1 = fmaf(sc4.y, h.y, sh4.y);
        float x2 = fmaf(sc4.z, h.z, sh4.z);
        float x3 = fmaf(sc4.w, h.w, sh4.w);

        float4 t = mm32(x0, x1, x2, x3, s_w1, s_b1, srcbase, r4);
        t.x = fmaxf(t.x, 0.f);
        t.y = fmaxf(t.y, 0.f);
        t.z = fmaxf(t.z, 0.f);
        t.w = fmaxf(t.w, 0.f);

        float o[6];
#pragma unroll
        for (int jj = 0; jj < 6; jj++) o[jj] = s_b2[c0 + jj];

#pragma unroll
        for (int kk = 0; kk < 8; kk++) {
            int src = srcbase + kk;
            float u0 = __shfl_sync(0xffffffffu, t.x, src);
            float u1 = __shfl_sync(0xffffffffu, t.y, src);
            float u2 = __shfl_sync(0xffffffffu, t.z, src);
            float u3 = __shfl_sync(0xffffffffu, t.w, src);
            const float* w0 = &s_w2[(4 * kk) * 41 + c0];
            const float* w1 = &s_w2[(4 * kk + 1) * 41 + c0];
            const float* w2r = &s_w2[(4 * kk + 2) * 41 + c0];
            const float* w3 = &s_w2[(4 * kk + 3) * 41 + c0];
#pragma unroll
            for (int jj = 0; jj < 6; jj++) {
                if (jj < nc) {
                    o[jj] = fmaf(u0, w0[jj], o[jj]);
                    o[jj] = fmaf(u1, w1[jj], o[jj]);
                    o[jj] = fmaf(u2, w2r[jj], o[jj]);
                    o[jj] = fmaf(u3, w3[jj], o[jj]);
                }
            }
        }
#pragma unroll
        for (int jj = 0; jj < 6; jj++)
            if (jj < nc) out[(size_t)v * 41 + c0 + jj] = o[jj];
    }
}

// ------------------------------------------------------------------
// launch: place2+padfill on side stream overlap wc+gemm; then tail.
// ------------------------------------------------------------------
static cudaStream_t g_side = nullptr;
static cudaEvent_t g_evFork = nullptr, g_evJoin = nullptr;

extern "C" void kernel_launch(void* const* d_in, const int* in_sizes, int n_in,
                              void* d_out, int out_size) {
    const float* x = (const float*)d_in[0];
    const int* ei = (const int*)d_in[1];
    const float* lin1_w = (const float*)d_in[2];
    const float* lin1_b = (const float*)d_in[3];
    const float* nn1_w1 = (const float*)d_in[4];
    const float* nn1_b1 = (const float*)d_in[5];
    const float* nn1_w2 = (const float*)d_in[6];
    const float* nn1_b2 = (const float*)d_in[7];
    const float* bn1_g = (const float*)d_in[8];
    const float* bn1_b = (const float*)d_in[9];
    const float* nn2_w1 = (const float*)d_in[10];
    const float* nn2_b1 = (const float*)d_in[11];
    const float* nn2_w2 = (const float*)d_in[12];
    const float* nn2_b2 = (const float*)d_in[13];
    const float* bn2_g = (const float*)d_in[14];
    const float* bn2_b = (const float*)d_in[15];
    const float* fc1_w = (const float*)d_in[16];
    const float* fc1_b = (const float*)d_in[17];
    const float* fc2_w = (const float*)d_in[18];
    const float* fc2_b = (const float*)d_in[19];
    float* out = (float*)d_out;

    if (!g_side) {
        int lo, hi;
        cudaDeviceGetStreamPriorityRange(&lo, &hi);
        cudaStreamCreateWithPriority(&g_side, cudaStreamNonBlocking, hi);
        cudaEventCreateWithFlags(&g_evFork, cudaEventDisableTiming);
        cudaEventCreateWithFlags(&g_evJoin, cudaEventDisableTiming);
        cudaFuncSetAttribute(gemm_kernel,
                             cudaFuncAttributeMaxDynamicSharedMemorySize,
                             GEMM_SMEM);
    }

    cudaEventRecord(g_evFork, 0);
    cudaStreamWaitEvent(g_side, g_evFork, 0);

    place2_kernel<<<256, 256, 0, g_side>>>(ei);                       // #1
    padfill_kernel<<<(NN + 255) / 256, 256, 0, g_side>>>();           // #2
    cudaEventRecord(g_evJoin, g_side);

    wc_kernel<<<(FF + 7) / 8, 256>>>(lin1_w, nn1_w1, lin1_b);         // #3
    gemm_kernel<<<(NN + BM - 1) / BM, 256, GEMM_SMEM>>>(x);           // #4 (profiled)

    cudaStreamWaitEvent(0, g_evJoin, 0);

    gmlp1_kernel<<<GSB, 256>>>(nn1_b1, nn1_w2, nn1_b2);               // #5
    gmlp2_kernel<<<GSB, 256>>>(nn2_w1, nn2_b1, nn2_w2, nn2_b2, bn1_g, bn1_b);
    head_kernel<<<GSB, 256>>>(fc1_w, fc1_b, fc2_w, fc2_b, bn2_g, bn2_b, out);
}

// round 16
// speedup vs baseline: 1.1913x; 1.1010x over previous
#include <cuda_runtime.h>
#include <cuda_fp16.h>
#include <cstdint>

#define NN 100000
#define EE 1600000
#define FF 602
#define FP 608   // padded K (wc zero-fills 602..607)
#define DEGMAX 64

// ------------------------------------------------------------------
// Scratch (static device globals)
// ------------------------------------------------------------------
__device__ __align__(16) __half g_whT[32 * FP];  // Wc^T fp16 [n][k]
__device__ float g_bc[32];
__device__ __align__(16) __half g_yh[(size_t)(NN + 1) * 32];   // y fp16
__device__ __align__(16) __half g_h1h[(size_t)(NN + 1) * 32];  // h1 fp16
__device__ float g_h2[(size_t)NN * 32];

__device__ int g_cnt[NN];                           // zero at start of replay
__device__ __align__(16) int g_pad[(size_t)NN * DEGMAX];  // padded adj lists

__device__ float g_sum1[32], g_sq1[32];
__device__ float g_sum2[32], g_sq2[32];

// ------------------------------------------------------------------
// small helpers
// ------------------------------------------------------------------
__device__ __forceinline__ float4 f4add(float4 a, float4 b) {
    return make_float4(a.x + b.x, a.y + b.y, a.z + b.z, a.w + b.w);
}

__device__ __forceinline__ float4 ld_h4(const __half* p) {
    uint2 u = *(const uint2*)p;
    __half2 h0 = *(__half2*)&u.x;
    __half2 h1 = *(__half2*)&u.y;
    float2 f0 = __half22float2(h0);
    float2 f1 = __half22float2(h1);
    return make_float4(f0.x, f0.y, f1.x, f1.y);
}

__device__ __forceinline__ void st_h4(__half* p, float4 v) {
    __half2 h0 = __floats2half2_rn(v.x, v.y);
    __half2 h1 = __floats2half2_rn(v.z, v.w);
    uint2 u;
    u.x = *(uint32_t*)&h0;
    u.y = *(uint32_t*)&h1;
    *(uint2*)p = u;
}

// pack float2 -> f16x2 (x in low half, y in high half)
__device__ __forceinline__ uint32_t cvt_h2(float2 p) {
    uint32_t h;
    asm("cvt.rn.f16x2.f32 %0, %1, %2;" : "=r"(h) : "f"(p.y), "f"(p.x));
    return h;
}

// ------------------------------------------------------------------
// place2: one-pass padded-CSR build (g_cnt zero on entry; head re-zeroes)
// ------------------------------------------------------------------
__global__ void __launch_bounds__(256) place2_kernel(const int* __restrict__ ei) {
    const int4* __restrict__ s4 = (const int4*)ei;
    const int4* __restrict__ d4 = (const int4*)(ei + EE);
    const int n4 = EE / 4;
    for (int i = blockIdx.x * 256 + threadIdx.x; i < n4; i += gridDim.x * 256) {
        int4 s = s4[i];
        int4 d = d4[i];
        int p0 = atomicAdd(&g_cnt[d.x], 1);
        int p1 = atomicAdd(&g_cnt[d.y], 1);
        int p2 = atomicAdd(&g_cnt[d.z], 1);
        int p3 = atomicAdd(&g_cnt[d.w], 1);
        g_pad[(size_t)d.x * DEGMAX + p0] = s.x;
        g_pad[(size_t)d.y * DEGMAX + p1] = s.y;
        g_pad[(size_t)d.z * DEGMAX + p2] = s.z;
        g_pad[(size_t)d.w * DEGMAX + p3] = s.w;
    }
}

// ------------------------------------------------------------------
// Wc = lin1_w @ nn1_w1 -> fp16 transposed; bc; zero BN sums
// ------------------------------------------------------------------
__global__ void __launch_bounds__(256) wc_kernel(
    const float* __restrict__ lw, const float* __restrict__ w1,
    const float* __restrict__ lb) {
    __shared__ float s_w1[64 * 32];
    const int tid = threadIdx.x;
    const int w = tid >> 5, lane = tid & 31;
    for (int i = tid; i < 64 * 32; i += 256) s_w1[i] = w1[i];
    __syncthreads();

    const int f = blockIdx.x * 8 + w;
    if (f < FF) {
        float r0 = lw[f * 64 + lane];
        float r1 = lw[f * 64 + 32 + lane];
        float acc0 = 0.f, acc1 = 0.f;
#pragma unroll
        for (int m = 0; m < 32; m++) {
            float u0 = __shfl_sync(0xffffffffu, r0, m);
            float u1 = __shfl_sync(0xffffffffu, r1, m);
            acc0 = fmaf(u0, s_w1[m * 32 + lane], acc0);
            acc1 = fmaf(u1, s_w1[(m + 32) * 32 + lane], acc1);
        }
        g_whT[lane * FP + f] = __float2half(acc0 + acc1);
    }

    if (blockIdx.x == 0) {
        if (tid < 32 * (FP - FF)) {  // zero pad cols 602..607
            int n = tid / (FP - FF);
            int f2 = FF + tid % (FP - FF);
            g_whT[n * FP + f2] = __float2half(0.f);
        }
        if (tid < 32) {
            float acc = 0.f;
#pragma unroll
            for (int m = 0; m < 64; m++)
                acc = fmaf(lb[m], s_w1[m * 32 + tid], acc);
            g_bc[tid] = acc;
            g_sum1[tid] = 0.f;
            g_sq1[tid] = 0.f;
            g_sum2[tid] = 0.f;
            g_sq2[tid] = 0.f;
        }
    }
}

// ------------------------------------------------------------------
// GEMM v8: fp16 single-MMA, BM=64, BK=32, 3-stage cp.async
// smem 38400B; y stored fp16
// ------------------------------------------------------------------
__device__ __forceinline__ void mma_f16(float* acc, uint32_t a0, uint32_t a1,
                                        uint32_t a2, uint32_t a3, uint32_t b0,
                                        uint32_t b1) {
    asm volatile(
        "mma.sync.aligned.m16n8k16.row.col.f32.f16.f16.f32 "
        "{%0,%1,%2,%3}, {%4,%5,%6,%7}, {%8,%9}, {%0,%1,%2,%3};\n"
        : "+f"(acc[0]), "+f"(acc[1]), "+f"(acc[2]), "+f"(acc[3])
        : "r"(a0), "r"(a1), "r"(a2), "r"(a3), "r"(b0), "r"(b1));
}

#define BM 64
#define AS_WORDS (BM * 40)   // f32 words per A stage (10240 B)
#define BS_WORDS (32 * 20)   // u32 words per B stage (2560 B)
#define NSTAGE 3
#define NT 19
#define GEMM_SMEM (NSTAGE * (AS_WORDS * 4 + BS_WORDS * 4))  // 38400

__global__ void __launch_bounds__(256) gemm_kernel(const float* __restrict__ x) {
    extern __shared__ char smem[];
    float* As = (float*)smem;
    uint32_t* Bs = (uint32_t*)(smem + NSTAGE * AS_WORDS * 4);

    const int tid = threadIdx.x;
    const int wid = tid >> 5, lane = tid & 31;
    const int g = lane >> 2, tig = lane & 3;
    const int mq = wid & 3;
    const int nh = wid >> 2;
    const int row0 = blockIdx.x * BM;

    const uint32_t* __restrict__ wt = (const uint32_t*)g_whT;

    const uint32_t asb = (uint32_t)__cvta_generic_to_shared(As);
    const uint32_t bsb = (uint32_t)__cvta_generic_to_shared(Bs);

    auto load_tile = [&](int t) {
        const int k0 = t * 32;
        const int buf = t % NSTAGE;
        // A: 64 rows x 32 k fp32, 8B cp.async each (x rows 8B-aligned)
#pragma unroll
        for (int it = 0; it < 4; it++) {
            int idx = it * 256 + tid;
            int r = idx >> 4, c2 = idx & 15;
            int grow = row0 + r;
            int k = k0 + c2 * 2;
            const float* src = x + (size_t)grow * FF + k;
            uint32_t dst =
                asb + (uint32_t)(buf * AS_WORDS + r * 40 + c2 * 2) * 4;
            int sz = (grow < NN && k < FF) ? 8 : 0;
            asm volatile("cp.async.ca.shared.global [%0], [%1], 8, %2;\n" ::
                             "r"(dst), "l"(src), "r"(sz));
        }
        // B: 32 rows x 32 k fp16 = 2KB; 128 threads x 16B
        if (tid < 128) {
            int n = tid >> 2, c = tid & 3;
            const uint32_t* src = wt + n * (FP / 2) + (k0 >> 1) + c * 4;
            uint32_t dst =
                bsb + (uint32_t)(buf * BS_WORDS + n * 20 + c * 4) * 4;
            asm volatile("cp.async.cg.shared.global [%0], [%1], 16;\n" ::
                             "r"(dst), "l"(src));
        }
        asm volatile("cp.async.commit_group;\n");
    };

    float acc[2][4] = {};

    load_tile(0);
    load_tile(1);

    for (int t = 0; t < NT; t++) {
        if (t < NT - 1) {
            asm volatile("cp.async.wait_group 1;\n");
        } else {
            asm volatile("cp.async.wait_group 0;\n");
        }
        __syncthreads();

        if (t + 2 < NT) load_tile(t + 2);

        const int b = t % NSTAGE;
        const float* A = As + b * AS_WORDS;
        const uint32_t* BS_ = Bs + b * BS_WORDS;

#pragma unroll
        for (int ks = 0; ks < 2; ks++) {
            const int rA = (mq * 16 + g) * 40 + ks * 16 + 2 * tig;
            uint32_t a0 = cvt_h2(*(const float2*)&A[rA]);
            uint32_t a1 = cvt_h2(*(const float2*)&A[rA + 8 * 40]);
            uint32_t a2 = cvt_h2(*(const float2*)&A[rA + 8]);
            uint32_t a3 = cvt_h2(*(const float2*)&A[rA + 8 * 40 + 8]);
#pragma unroll
            for (int nt = 0; nt < 2; nt++) {
                const int rB = (nh * 16 + nt * 8 + g) * 20 + ks * 8 + tig;
                uint32_t b0 = BS_[rB];
                uint32_t b1 = BS_[rB + 4];
                mma_f16(acc[nt], a0, a1, a2, a3, b0, b1);
            }
        }
    }

    const int ra = row0 + mq * 16 + g;
#pragma unroll
    for (int nt = 0; nt < 2; nt++) {
        int col = nh * 16 + nt * 8 + 2 * tig;
        float2 bias = *(const float2*)&g_bc[col];
        if (ra < NN) {
            __half2 h = __floats2half2_rn(acc[nt][0] + bias.x,
                                          acc[nt][1] + bias.y);
            *(__half2*)&g_yh[(size_t)ra * 32 + col] = h;
        }
        if (ra + 8 < NN) {
            __half2 h = __floats2half2_rn(acc[nt][2] + bias.x,
                                          acc[nt][3] + bias.y);
            *(__half2*)&g_yh[(size_t)(ra + 8) * 32 + col] = h;
        }
    }
}

// ------------------------------------------------------------------
// gather4h (r13-proven): padded lists; fp16 rows; 8 rows in flight
// ------------------------------------------------------------------
__device__ __forceinline__ float4 gather_row4h(const __half* __restrict__ src,
                                               int v, int r4, int cnt, int mc) {
    const size_t base = (size_t)v * DEGMAX;
    float4 a0 = ld_h4(&src[(size_t)v * 32 + r4]);
    float4 a1 = make_float4(0.f, 0.f, 0.f, 0.f);
    float4 a2 = a1, a3 = a1;
    int i = 0;
    for (; i + 8 <= mc; i += 8) {
        int4 sa = *(const int4*)&g_pad[base + i];
        int4 sb = *(const int4*)&g_pad[base + i + 4];
        float4 t0 = ld_h4(&src[(size_t)sa.x * 32 + r4]);
        float4 t1 = ld_h4(&src[(size_t)sa.y * 32 + r4]);
        float4 t2 = ld_h4(&src[(size_t)sa.z * 32 + r4]);
        float4 t3 = ld_h4(&src[(size_t)sa.w * 32 + r4]);
        float4 t4 = ld_h4(&src[(size_t)sb.x * 32 + r4]);
        float4 t5 = ld_h4(&src[(size_t)sb.y * 32 + r4]);
        float4 t6 = ld_h4(&src[(size_t)sb.z * 32 + r4]);
        float4 t7 = ld_h4(&src[(size_t)sb.w * 32 + r4]);
        if (i < cnt) a0 = f4add(a0, t0);
        if (i + 1 < cnt) a1 = f4add(a1, t1);
        if (i + 2 < cnt) a2 = f4add(a2, t2);
        if (i + 3 < cnt) a3 = f4add(a3, t3);
        if (i + 4 < cnt) a0 = f4add(a0, t4);
        if (i + 5 < cnt) a1 = f4add(a1, t5);
        if (i + 6 < cnt) a2 = f4add(a2, t6);
        if (i + 7 < cnt) a3 = f4add(a3, t7);
    }
    for (; i < mc; i++) {
        int s = g_pad[base + i];
        float4 t = ld_h4(&src[(size_t)s * 32 + r4]);
        if (i < cnt) a0 = f4add(a0, t);
    }
    return f4add(f4add(a0, a1), f4add(a2, a3));
}

// 32x32 matmul in 4-node layout
__device__ __forceinline__ float4 mm32(float T0, float T1, float T2, float T3,
                                       const float* __restrict__ sw,
                                       const float* __restrict__ sb,
                                       int srcbase, int r4) {
    float4 o = *(const float4*)&sb[r4];
#pragma unroll
    for (int kk = 0; kk < 8; kk++) {
        int src = srcbase + kk;
        float u0 = __shfl_sync(0xffffffffu, T0, src);
        float u1 = __shfl_sync(0xffffffffu, T1, src);
        float u2 = __shfl_sync(0xffffffffu, T2, src);
        float u3 = __shfl_sync(0xffffffffu, T3, src);
        float4 w0 = *(const float4*)&sw[(4 * kk) * 32 + r4];
        float4 w1 = *(const float4*)&sw[(4 * kk + 1) * 32 + r4];
        float4 w2 = *(const float4*)&sw[(4 * kk + 2) * 32 + r4];
        float4 w3 = *(const float4*)&sw[(4 * kk + 3) * 32 + r4];
        o.x = fmaf(u0, w0.x, o.x); o.y = fmaf(u0, w0.y, o.y);
        o.z = fmaf(u0, w0.z, o.z); o.w = fmaf(u0, w0.w, o.w);
        o.x = fmaf(u1, w1.x, o.x); o.y = fmaf(u1, w1.y, o.y);
        o.z = fmaf(u1, w1.z, o.z); o.w = fmaf(u1, w1.w, o.w);
        o.x = fmaf(u2, w2.x, o.x); o.y = fmaf(u2, w2.y, o.y);
        o.z = fmaf(u2, w2.z, o.z); o.w = fmaf(u2, w2.w, o.w);
        o.x = fmaf(u3, w3.x, o.x); o.y = fmaf(u3, w3.y, o.y);
        o.z = fmaf(u3, w3.z, o.z); o.w = fmaf(u3, w3.w, o.w);
    }
    return o;
}

#define NCHUNK (NN / 4)  // 25000
#define GSB 592          // 148 SM x 4 blocks: one resident wave

// ------------------------------------------------------------------
// gmlp1: a = y[v]+sum_nbr (fp16 src); t = relu(a+b1); h1 = t@w2+b2
// ------------------------------------------------------------------
__global__ void __launch_bounds__(256, 4) gmlp1_kernel(
    const float* __restrict__ b1, const float* __restrict__ w2,
    const float* __restrict__ b2) {
    __shared__ __align__(16) float s_w2[1024];
    __shared__ __align__(16) float s_b1[32], s_b2[32];
    __shared__ float s_red[2][8][32];
    const int tid = threadIdx.x;
    for (int i = tid; i < 1024; i += 256) s_w2[i] = w2[i];
    if (tid < 32) { s_b1[tid] = b1[tid]; s_b2[tid] = b2[tid]; }
    __syncthreads();

    const int w = tid >> 5, lane = tid & 31;
    const int q = lane >> 3, r4 = (lane & 7) * 4;
    const int srcbase = lane & 24;
    float4 b1v = *(const float4*)&s_b1[r4];

    float4 ssum = make_float4(0.f, 0.f, 0.f, 0.f), ssq = ssum;

    for (int c = blockIdx.x * 8 + w; c < NCHUNK; c += GSB * 8) {
        const int v = c * 4 + q;
        const int cnt = g_cnt[v];
        int mc = cnt;
        mc = max(mc, __shfl_xor_sync(0xffffffffu, mc, 8));
        mc = max(mc, __shfl_xor_sync(0xffffffffu, mc, 16));

        float4 a = gather_row4h(g_yh, v, r4, cnt, mc);
        float t0 = fmaxf(a.x + b1v.x, 0.f);
        float t1 = fmaxf(a.y + b1v.y, 0.f);
        float t2 = fmaxf(a.z + b1v.z, 0.f);
        float t3 = fmaxf(a.w + b1v.w, 0.f);

        float4 o = mm32(t0, t1, t2, t3, s_w2, s_b2, srcbase, r4);
        st_h4(&g_h1h[(size_t)v * 32 + r4], o);
        ssum = f4add(ssum, o);
        ssq.x = fmaf(o.x, o.x, ssq.x);
        ssq.y = fmaf(o.y, o.y, ssq.y);
        ssq.z = fmaf(o.z, o.z, ssq.z);
        ssq.w = fmaf(o.w, o.w, ssq.w);
    }

#pragma unroll
    for (int m = 8; m <= 16; m <<= 1) {
        ssum.x += __shfl_xor_sync(0xffffffffu, ssum.x, m);
        ssum.y += __shfl_xor_sync(0xffffffffu, ssum.y, m);
        ssum.z += __shfl_xor_sync(0xffffffffu, ssum.z, m);
        ssum.w += __shfl_xor_sync(0xffffffffu, ssum.w, m);
        ssq.x += __shfl_xor_sync(0xffffffffu, ssq.x, m);
        ssq.y += __shfl_xor_sync(0xffffffffu, ssq.y, m);
        ssq.z += __shfl_xor_sync(0xffffffffu, ssq.z, m);
        ssq.w += __shfl_xor_sync(0xffffffffu, ssq.w, m);
    }
    if (lane < 8) {
        *(float4*)&s_red[0][w][r4] = ssum;
        *(float4*)&s_red[1][w][r4] = ssq;
    }
    __syncthreads();
    if (tid < 32) {
        float s = 0.f, qq = 0.f;
#pragma unroll
        for (int ww = 0; ww < 8; ww++) {
            s += s_red[0][ww][tid];
            qq += s_red[1][ww][tid];
        }
        atomicAdd(&g_sum1[tid], s);
        atomicAdd(&g_sq1[tid], qq);
    }
}

// ------------------------------------------------------------------
// gmlp2: BN1 local; m = sc*(h1[v]+sum)+(deg+1)*sh; 2 matmuls (+BN2 stats)
// ------------------------------------------------------------------
__global__ void __launch_bounds__(256, 4) gmlp2_kernel(
    const float* __restrict__ w1, const float* __restrict__ b1,
    const float* __restrict__ w2, const float* __restrict__ b2,
    const float* __restrict__ bng, const float* __restrict__ bnb) {
    __shared__ __align__(16) float s_w1[1024], s_w2[1024];
    __shared__ __align__(16) float s_b1[32], s_b2[32];
    __shared__ float s_red[2][8][32];
    const int tid = threadIdx.x;
    for (int i = tid; i < 1024; i += 256) {
        s_w1[i] = w1[i];
        s_w2[i] = w2[i];
    }
    if (tid < 32) { s_b1[tid] = b1[tid]; s_b2[tid] = b2[tid]; }
    __syncthreads();

    const int w = tid >> 5, lane = tid & 31;
    const int q = lane >> 3, r4 = (lane & 7) * 4;
    const int srcbase = lane & 24;

    float4 gs = *(const float4*)&g_sum1[r4];
    float4 gq = *(const float4*)&g_sq1[r4];
    float4 gg = make_float4(bng[r4], bng[r4 + 1], bng[r4 + 2], bng[r4 + 3]);
    float4 gb = make_float4(bnb[r4], bnb[r4 + 1], bnb[r4 + 2], bnb[r4 + 3]);
    float4 sc4, sh4;
    {
        float m0 = gs.x / NN, m1 = gs.y / NN, m2 = gs.z / NN, m3 = gs.w / NN;
        sc4.x = gg.x * rsqrtf(fmaxf(gq.x / NN - m0 * m0, 0.f) + 1e-5f);
        sc4.y = gg.y * rsqrtf(fmaxf(gq.y / NN - m1 * m1, 0.f) + 1e-5f);
        sc4.z = gg.z * rsqrtf(fmaxf(gq.z / NN - m2 * m2, 0.f) + 1e-5f);
        sc4.w = gg.w * rsqrtf(fmaxf(gq.w / NN - m3 * m3, 0.f) + 1e-5f);
        sh4.x = gb.x - m0 * sc4.x;
        sh4.y = gb.y - m1 * sc4.y;
        sh4.z = gb.z - m2 * sc4.z;
        sh4.w = gb.w - m3 * sc4.w;
    }

    float4 ssum = make_float4(0.f, 0.f, 0.f, 0.f), ssq = ssum;

    for (int c = blockIdx.x * 8 + w; c < NCHUNK; c += GSB * 8) {
        const int v = c * 4 + q;
        const int cnt = g_cnt[v];
        int mc = cnt;
        mc = max(mc, __shfl_xor_sync(0xffffffffu, mc, 8));
        mc = max(mc, __shfl_xor_sync(0xffffffffu, mc, 16));

        float4 a = gather_row4h(g_h1h, v, r4, cnt, mc);
        float degp1 = (float)(cnt + 1);
        float m0 = fmaf(sc4.x, a.x, degp1 * sh4.x);
        float m1 = fmaf(sc4.y, a.y, degp1 * sh4.y);
        float m2 = fmaf(sc4.z, a.z, degp1 * sh4.z);
        float m3 = fmaf(sc4.w, a.w, degp1 * sh4.w);

        float4 t = mm32(m0, m1, m2, m3, s_w1, s_b1, srcbase, r4);
        t.x = fmaxf(t.x, 0.f);
        t.y = fmaxf(t.y, 0.f);
        t.z = fmaxf(t.z, 0.f);
        t.w = fmaxf(t.w, 0.f);

        float4 o = mm32(t.x, t.y, t.z, t.w, s_w2, s_b2, srcbase, r4);
        *(float4*)&g_h2[(size_t)v * 32 + r4] = o;
        ssum = f4add(ssum, o);
        ssq.x = fmaf(o.x, o.x, ssq.x);
        ssq.y = fmaf(o.y, o.y, ssq.y);
        ssq.z = fmaf(o.z, o.z, ssq.z);
        ssq.w = fmaf(o.w, o.w, ssq.w);
    }

#pragma unroll
    for (int m = 8; m <= 16; m <<= 1) {
        ssum.x += __shfl_xor_sync(0xffffffffu, ssum.x, m);
        ssum.y += __shfl_xor_sync(0xffffffffu, ssum.y, m);
        ssum.z += __shfl_xor_sync(0xffffffffu, ssum.z, m);
        ssum.w += __shfl_xor_sync(0xffffffffu, ssum.w, m);
        ssq.x += __shfl_xor_sync(0xffffffffu, ssq.x, m);
        ssq.y += __shfl_xor_sync(0xffffffffu, ssq.y, m);
        ssq.z += __shfl_xor_sync(0xffffffffu, ssq.z, m);
        ssq.w += __shfl_xor_sync(0xffffffffu, ssq.w, m);
    }
    if (lane < 8) {
        *(float4*)&s_red[0][w][r4] = ssum;
        *(float4*)&s_red[1][w][r4] = ssq;
    }
    __syncthreads();
    if (tid < 32) {
        float s = 0.f, qq = 0.f;
#pragma unroll
        for (int ww = 0; ww < 8; ww++) {
            s += s_red[0][ww][tid];
            qq += s_red[1][ww][tid];
        }
        atomicAdd(&g_sum2[tid], s);
        atomicAdd(&g_sq2[tid], qq);
    }
}

// ------------------------------------------------------------------
// head: 4-node layout; BN2 local; fc1 via mm32; fc2 in 6-col strips.
// Re-zeroes g_cnt for the next graph replay.
// ------------------------------------------------------------------
__global__ void __launch_bounds__(256, 4) head_kernel(
    const float* __restrict__ fc1w, const float* __restrict__ fc1b,
    const float* __restrict__ fc2w, const float* __restrict__ fc2b,
    const float* __restrict__ bng, const float* __restrict__ bnb,
    float* __restrict__ out) {
    __shared__ __align__(16) float s_w1[1024];
    __shared__ float s_w2[32 * 41];
    __shared__ __align__(16) float s_b1[32];
    __shared__ float s_b2[48];
    const int tid = threadIdx.x;
    for (int i = tid; i < 1024; i += 256) s_w1[i] = fc1w[i];
    for (int i = tid; i < 32 * 41; i += 256) s_w2[i] = fc2w[i];
    if (tid < 32) s_b1[tid] = fc1b[tid];
    if (tid < 41) s_b2[tid] = fc2b[tid];
    if (tid >= 41 && tid < 48) s_b2[tid] = 0.f;
    __syncthreads();

    const int w = tid >> 5, lane = tid & 31;
    const int q = lane >> 3, r = lane & 7, r4 = r * 4;
    const int srcbase = lane & 24;

    float4 gs = *(const float4*)&g_sum2[r4];
    float4 gq = *(const float4*)&g_sq2[r4];
    float4 sc4, sh4;
    {
        float m0 = gs.x / NN, m1 = gs.y / NN, m2 = gs.z / NN, m3 = gs.w / NN;
        sc4.x = bng[r4] * rsqrtf(fmaxf(gq.x / NN - m0 * m0, 0.f) + 1e-5f);
        sc4.y = bng[r4 + 1] * rsqrtf(fmaxf(gq.y / NN - m1 * m1, 0.f) + 1e-5f);
        sc4.z = bng[r4 + 2] * rsqrtf(fmaxf(gq.z / NN - m2 * m2, 0.f) + 1e-5f);
        sc4.w = bng[r4 + 3] * rsqrtf(fmaxf(gq.w / NN - m3 * m3, 0.f) + 1e-5f);
        sh4.x = bnb[r4] - m0 * sc4.x;
        sh4.y = bnb[r4 + 1] - m1 * sc4.y;
        sh4.z = bnb[r4 + 2] - m2 * sc4.z;
        sh4.w = bnb[r4 + 3] - m3 * sc4.w;
    }

    const int c0 = r * 6;
    const int nc = max(0, min(6, 41 - c0));

    for (int c = blockIdx.x * 8 + w; c < NCHUNK; c += GSB * 8) {
        const int v = c * 4 + q;
        if (r == 0) g_cnt[v] = 0;  // reset padded-CSR counters for next replay
        float4 h = *(const float4*)&g_h2[(size_t)v * 32 + r4];
        float x0 = fmaf(sc4.x, h.x, sh4.x);
        float x1 = fmaf(sc4.y, h.y, sh4.y);
        float x2 = fmaf(sc4.z, h.z, sh4.z);
        float x3 = fmaf(sc4.w, h.w, sh4.w);

        float4 t = mm32(x0, x1, x2, x3, s_w1, s_b1, srcbase, r4);
        t.x = fmaxf(t.x, 0.f);
        t.y = fmaxf(t.y, 0.f);
        t.z = fmaxf(t.z, 0.f);
        t.w = fmaxf(t.w, 0.f);

        float o[6];
#pragma unroll
        for (int jj = 0; jj < 6; jj++) o[jj] = s_b2[c0 + jj];

#pragma unroll
        for (int kk = 0; kk < 8; kk++) {
            int src = srcbase + kk;
            float u0 = __shfl_sync(0xffffffffu, t.x, src);
            float u1 = __shfl_sync(0xffffffffu, t.y, src);
            float u2 = __shfl_sync(0xffffffffu, t.z, src);
            float u3 = __shfl_sync(0xffffffffu, t.w, src);
            const float* w0 = &s_w2[(4 * kk) * 41 + c0];
            const float* w1 = &s_w2[(4 * kk + 1) * 41 + c0];
            const float* w2r = &s_w2[(4 * kk + 2) * 41 + c0];
            const float* w3 = &s_w2[(4 * kk + 3) * 41 + c0];
#pragma unroll
            for (int jj = 0; jj < 6; jj++) {
                if (jj < nc) {
                    o[jj] = fmaf(u0, w0[jj], o[jj]);
                    o[jj] = fmaf(u1, w1[jj], o[jj]);
                    o[jj] = fmaf(u2, w2r[jj], o[jj]);
                    o[jj] = fmaf(u3, w3[jj], o[jj]);
                }
            }
        }
#pragma unroll
        for (int jj = 0; jj < 6; jj++)
            if (jj < nc) out[(size_t)v * 41 + c0 + jj] = o[jj];
    }
}

// ------------------------------------------------------------------
// launch: r13 structure; place2 on side stream overlaps wc+gemm.
// ------------------------------------------------------------------
static cudaStream_t g_side = nullptr;
static cudaEvent_t g_evFork = nullptr, g_evJoin = nullptr;

extern "C" void kernel_launch(void* const* d_in, const int* in_sizes, int n_in,
                              void* d_out, int out_size) {
    const float* x = (const float*)d_in[0];
    const int* ei = (const int*)d_in[1];
    const float* lin1_w = (const float*)d_in[2];
    const float* lin1_b = (const float*)d_in[3];
    const float* nn1_w1 = (const float*)d_in[4];
    const float* nn1_b1 = (const float*)d_in[5];
    const float* nn1_w2 = (const float*)d_in[6];
    const float* nn1_b2 = (const float*)d_in[7];
    const float* bn1_g = (const float*)d_in[8];
    const float* bn1_b = (const float*)d_in[9];
    const float* nn2_w1 = (const float*)d_in[10];
    const float* nn2_b1 = (const float*)d_in[11];
    const float* nn2_w2 = (const float*)d_in[12];
    const float* nn2_b2 = (const float*)d_in[13];
    const float* bn2_g = (const float*)d_in[14];
    const float* bn2_b = (const float*)d_in[15];
    const float* fc1_w = (const float*)d_in[16];
    const float* fc1_b = (const float*)d_in[17];
    const float* fc2_w = (const float*)d_in[18];
    const float* fc2_b = (const float*)d_in[19];
    float* out = (float*)d_out;

    if (!g_side) {
        int lo, hi;
        cudaDeviceGetStreamPriorityRange(&lo, &hi);
        cudaStreamCreateWithPriority(&g_side, cudaStreamNonBlocking, hi);
        cudaEventCreateWithFlags(&g_evFork, cudaEventDisableTiming);
        cudaEventCreateWithFlags(&g_evJoin, cudaEventDisableTiming);
        cudaFuncSetAttribute(gemm_kernel,
                             cudaFuncAttributeMaxDynamicSharedMemorySize,
                             GEMM_SMEM);
    }

    cudaEventRecord(g_evFork, 0);
    cudaStreamWaitEvent(g_side, g_evFork, 0);

    place2_kernel<<<256, 256, 0, g_side>>>(ei);                       // #1
    cudaEventRecord(g_evJoin, g_side);

    wc_kernel<<<(FF + 7) / 8, 256>>>(lin1_w, nn1_w1, lin1_b);         // #2
    gemm_kernel<<<(NN + BM - 1) / BM, 256, GEMM_SMEM>>>(x);           // #3

    cudaStreamWaitEvent(0, g_evJoin, 0);

    gmlp1_kernel<<<GSB, 256>>>(nn1_b1, nn1_w2, nn1_b2);               // #4 (profiled)
    gmlp2_kernel<<<GSB, 256>>>(nn2_w1, nn2_b1, nn2_w2, nn2_b2, bn1_g, bn1_b);
    head_kernel<<<GSB, 256>>>(fc1_w, fc1_b, fc2_w, fc2_b, bn2_g, bn2_b, out);
}

// round 17
// speedup vs baseline: 1.2041x; 1.0108x over previous
#include <cuda_runtime.h>
#include <cuda_fp16.h>
#include <cstdint>

#define NN 100000
#define EE 1600000
#define FF 602
#define FP 608   // padded K (wc zero-fills 602..607)
#define DEGMAX 64

// ------------------------------------------------------------------
// Scratch (static device globals)
// ------------------------------------------------------------------
__device__ __align__(16) __half g_whT[32 * FP];  // Wc^T fp16 [n][k]
__device__ float g_bc[32];
__device__ __align__(16) __half g_yh[(size_t)(NN + 1) * 32];   // y fp16
__device__ __align__(16) __half g_h1h[(size_t)(NN + 1) * 32];  // h1 fp16
__device__ float g_h2[(size_t)NN * 32];

__device__ int g_cnt[NN];                           // zero at start of replay
__device__ __align__(16) int g_pad[(size_t)NN * DEGMAX];  // padded adj lists

__device__ float g_sum1[32], g_sq1[32];
__device__ float g_sum2[32], g_sq2[32];

// software grid barrier state (gen is monotonic across replays)
__device__ int g_bar_cnt = 0;
__device__ volatile int g_bar_gen = 0;

// ------------------------------------------------------------------
// small helpers
// ------------------------------------------------------------------
__device__ __forceinline__ float4 f4add(float4 a, float4 b) {
    return make_float4(a.x + b.x, a.y + b.y, a.z + b.z, a.w + b.w);
}

__device__ __forceinline__ float4 ld_h4(const __half* p) {
    uint2 u = *(const uint2*)p;
    __half2 h0 = *(__half2*)&u.x;
    __half2 h1 = *(__half2*)&u.y;
    float2 f0 = __half22float2(h0);
    float2 f1 = __half22float2(h1);
    return make_float4(f0.x, f0.y, f1.x, f1.y);
}

__device__ __forceinline__ void st_h4(__half* p, float4 v) {
    __half2 h0 = __floats2half2_rn(v.x, v.y);
    __half2 h1 = __floats2half2_rn(v.z, v.w);
    uint2 u;
    u.x = *(uint32_t*)&h0;
    u.y = *(uint32_t*)&h1;
    *(uint2*)p = u;
}

__device__ __forceinline__ uint32_t cvt_h2(float2 p) {
    uint32_t h;
    asm("cvt.rn.f16x2.f32 %0, %1, %2;" : "=r"(h) : "f"(p.y), "f"(p.x));
    return h;
}

// all-resident-wave grid barrier (grid sized to one wave)
__device__ __forceinline__ void grid_barrier(int nblocks) {
    __threadfence();
    __syncthreads();
    if (threadIdx.x == 0) {
        int gen = g_bar_gen;
        if (atomicAdd(&g_bar_cnt, 1) == nblocks - 1) {
            g_bar_cnt = 0;
            __threadfence();
            g_bar_gen = gen + 1;
        } else {
            while (g_bar_gen == gen) __nanosleep(32);
        }
    }
    __syncthreads();
}

// ------------------------------------------------------------------
// place2: one-pass padded-CSR build (g_cnt zero on entry; tail re-zeroes)
// ------------------------------------------------------------------
__global__ void __launch_bounds__(256) place2_kernel(const int* __restrict__ ei) {
    const int4* __restrict__ s4 = (const int4*)ei;
    const int4* __restrict__ d4 = (const int4*)(ei + EE);
    const int n4 = EE / 4;
    for (int i = blockIdx.x * 256 + threadIdx.x; i < n4; i += gridDim.x * 256) {
        int4 s = s4[i];
        int4 d = d4[i];
        int p0 = atomicAdd(&g_cnt[d.x], 1);
        int p1 = atomicAdd(&g_cnt[d.y], 1);
        int p2 = atomicAdd(&g_cnt[d.z], 1);
        int p3 = atomicAdd(&g_cnt[d.w], 1);
        g_pad[(size_t)d.x * DEGMAX + p0] = s.x;
        g_pad[(size_t)d.y * DEGMAX + p1] = s.y;
        g_pad[(size_t)d.z * DEGMAX + p2] = s.z;
        g_pad[(size_t)d.w * DEGMAX + p3] = s.w;
    }
}

// ------------------------------------------------------------------
// Wc = lin1_w @ nn1_w1 -> fp16 transposed; bc; zero BN sums
// ------------------------------------------------------------------
__global__ void __launch_bounds__(256) wc_kernel(
    const float* __restrict__ lw, const float* __restrict__ w1,
    const float* __restrict__ lb) {
    __shared__ float s_w1[64 * 32];
    const int tid = threadIdx.x;
    const int w = tid >> 5, lane = tid & 31;
    for (int i = tid; i < 64 * 32; i += 256) s_w1[i] = w1[i];
    __syncthreads();

    const int f = blockIdx.x * 8 + w;
    if (f < FF) {
        float r0 = lw[f * 64 + lane];
        float r1 = lw[f * 64 + 32 + lane];
        float acc0 = 0.f, acc1 = 0.f;
#pragma unroll
        for (int m = 0; m < 32; m++) {
            float u0 = __shfl_sync(0xffffffffu, r0, m);
            float u1 = __shfl_sync(0xffffffffu, r1, m);
            acc0 = fmaf(u0, s_w1[m * 32 + lane], acc0);
            acc1 = fmaf(u1, s_w1[(m + 32) * 32 + lane], acc1);
        }
        g_whT[lane * FP + f] = __float2half(acc0 + acc1);
    }

    if (blockIdx.x == 0) {
        if (tid < 32 * (FP - FF)) {
            int n = tid / (FP - FF);
            int f2 = FF + tid % (FP - FF);
            g_whT[n * FP + f2] = __float2half(0.f);
        }
        if (tid < 32) {
            float acc = 0.f;
#pragma unroll
            for (int m = 0; m < 64; m++)
                acc = fmaf(lb[m], s_w1[m * 32 + tid], acc);
            g_bc[tid] = acc;
            g_sum1[tid] = 0.f;
            g_sq1[tid] = 0.f;
            g_sum2[tid] = 0.f;
            g_sq2[tid] = 0.f;
        }
    }
}

// ------------------------------------------------------------------
// GEMM (r16-proven, ~56us): fp16 single-MMA, BM=64, 3-stage cp.async
// ------------------------------------------------------------------
__device__ __forceinline__ void mma_f16(float* acc, uint32_t a0, uint32_t a1,
                                        uint32_t a2, uint32_t a3, uint32_t b0,
                                        uint32_t b1) {
    asm volatile(
        "mma.sync.aligned.m16n8k16.row.col.f32.f16.f16.f32 "
        "{%0,%1,%2,%3}, {%4,%5,%6,%7}, {%8,%9}, {%0,%1,%2,%3};\n"
        : "+f"(acc[0]), "+f"(acc[1]), "+f"(acc[2]), "+f"(acc[3])
        : "r"(a0), "r"(a1), "r"(a2), "r"(a3), "r"(b0), "r"(b1));
}

#define BM 64
#define AS_WORDS (BM * 40)
#define BS_WORDS (32 * 20)
#define NSTAGE 3
#define NT 19
#define GEMM_SMEM (NSTAGE * (AS_WORDS * 4 + BS_WORDS * 4))  // 38400

__global__ void __launch_bounds__(256) gemm_kernel(const float* __restrict__ x) {
    extern __shared__ char smem[];
    float* As = (float*)smem;
    uint32_t* Bs = (uint32_t*)(smem + NSTAGE * AS_WORDS * 4);

    const int tid = threadIdx.x;
    const int wid = tid >> 5, lane = tid & 31;
    const int g = lane >> 2, tig = lane & 3;
    const int mq = wid & 3;
    const int nh = wid >> 2;
    const int row0 = blockIdx.x * BM;

    const uint32_t* __restrict__ wt = (const uint32_t*)g_whT;

    const uint32_t asb = (uint32_t)__cvta_generic_to_shared(As);
    const uint32_t bsb = (uint32_t)__cvta_generic_to_shared(Bs);

    auto load_tile = [&](int t) {
        const int k0 = t * 32;
        const int buf = t % NSTAGE;
#pragma unroll
        for (int it = 0; it < 4; it++) {
            int idx = it * 256 + tid;
            int r = idx >> 4, c2 = idx & 15;
            int grow = row0 + r;
            int k = k0 + c2 * 2;
            const float* src = x + (size_t)grow * FF + k;
            uint32_t dst =
                asb + (uint32_t)(buf * AS_WORDS + r * 40 + c2 * 2) * 4;
            int sz = (grow < NN && k < FF) ? 8 : 0;
            asm volatile("cp.async.ca.shared.global [%0], [%1], 8, %2;\n" ::
                             "r"(dst), "l"(src), "r"(sz));
        }
        if (tid < 128) {
            int n = tid >> 2, c = tid & 3;
            const uint32_t* src = wt + n * (FP / 2) + (k0 >> 1) + c * 4;
            uint32_t dst =
                bsb + (uint32_t)(buf * BS_WORDS + n * 20 + c * 4) * 4;
            asm volatile("cp.async.cg.shared.global [%0], [%1], 16;\n" ::
                             "r"(dst), "l"(src));
        }
        asm volatile("cp.async.commit_group;\n");
    };

    float acc[2][4] = {};

    load_tile(0);
    load_tile(1);

    for (int t = 0; t < NT; t++) {
        if (t < NT - 1) {
            asm volatile("cp.async.wait_group 1;\n");
        } else {
            asm volatile("cp.async.wait_group 0;\n");
        }
        __syncthreads();

        if (t + 2 < NT) load_tile(t + 2);

        const int b = t % NSTAGE;
        const float* A = As + b * AS_WORDS;
        const uint32_t* BS_ = Bs + b * BS_WORDS;

#pragma unroll
        for (int ks = 0; ks < 2; ks++) {
            const int rA = (mq * 16 + g) * 40 + ks * 16 + 2 * tig;
            uint32_t a0 = cvt_h2(*(const float2*)&A[rA]);
            uint32_t a1 = cvt_h2(*(const float2*)&A[rA + 8 * 40]);
            uint32_t a2 = cvt_h2(*(const float2*)&A[rA + 8]);
            uint32_t a3 = cvt_h2(*(const float2*)&A[rA + 8 * 40 + 8]);
#pragma unroll
            for (int nt = 0; nt < 2; nt++) {
                const int rB = (nh * 16 + nt * 8 + g) * 20 + ks * 8 + tig;
                uint32_t b0 = BS_[rB];
                uint32_t b1 = BS_[rB + 4];
                mma_f16(acc[nt], a0, a1, a2, a3, b0, b1);
            }
        }
    }

    const int ra = row0 + mq * 16 + g;
#pragma unroll
    for (int nt = 0; nt < 2; nt++) {
        int col = nh * 16 + nt * 8 + 2 * tig;
        float2 bias = *(const float2*)&g_bc[col];
        if (ra < NN) {
            __half2 h = __floats2half2_rn(acc[nt][0] + bias.x,
                                          acc[nt][1] + bias.y);
            *(__half2*)&g_yh[(size_t)ra * 32 + col] = h;
        }
        if (ra + 8 < NN) {
            __half2 h = __floats2half2_rn(acc[nt][2] + bias.x,
                                          acc[nt][3] + bias.y);
            *(__half2*)&g_yh[(size_t)(ra + 8) * 32 + col] = h;
        }
    }
}

// ------------------------------------------------------------------
// gather4h: padded lists; fp16 rows; 8 rows in flight
// ------------------------------------------------------------------
__device__ __forceinline__ float4 gather_row4h(const __half* __restrict__ src,
                                               int v, int r4, int cnt, int mc) {
    const size_t base = (size_t)v * DEGMAX;
    float4 a0 = ld_h4(&src[(size_t)v * 32 + r4]);
    float4 a1 = make_float4(0.f, 0.f, 0.f, 0.f);
    float4 a2 = a1, a3 = a1;
    int i = 0;
    for (; i + 8 <= mc; i += 8) {
        int4 sa = *(const int4*)&g_pad[base + i];
        int4 sb = *(const int4*)&g_pad[base + i + 4];
        float4 t0 = ld_h4(&src[(size_t)sa.x * 32 + r4]);
        float4 t1 = ld_h4(&src[(size_t)sa.y * 32 + r4]);
        float4 t2 = ld_h4(&src[(size_t)sa.z * 32 + r4]);
        float4 t3 = ld_h4(&src[(size_t)sa.w * 32 + r4]);
        float4 t4 = ld_h4(&src[(size_t)sb.x * 32 + r4]);
        float4 t5 = ld_h4(&src[(size_t)sb.y * 32 + r4]);
        float4 t6 = ld_h4(&src[(size_t)sb.z * 32 + r4]);
        float4 t7 = ld_h4(&src[(size_t)sb.w * 32 + r4]);
        if (i < cnt) a0 = f4add(a0, t0);
        if (i + 1 < cnt) a1 = f4add(a1, t1);
        if (i + 2 < cnt) a2 = f4add(a2, t2);
        if (i + 3 < cnt) a3 = f4add(a3, t3);
        if (i + 4 < cnt) a0 = f4add(a0, t4);
        if (i + 5 < cnt) a1 = f4add(a1, t5);
        if (i + 6 < cnt) a2 = f4add(a2, t6);
        if (i + 7 < cnt) a3 = f4add(a3, t7);
    }
    for (; i < mc; i++) {
        int s = g_pad[base + i];
        float4 t = ld_h4(&src[(size_t)s * 32 + r4]);
        if (i < cnt) a0 = f4add(a0, t);
    }
    return f4add(f4add(a0, a1), f4add(a2, a3));
}

// 32x32 matmul in 4-node layout
__device__ __forceinline__ float4 mm32(float T0, float T1, float T2, float T3,
                                       const float* __restrict__ sw,
                                       const float* __restrict__ sb,
                                       int srcbase, int r4) {
    float4 o = *(const float4*)&sb[r4];
#pragma unroll
    for (int kk = 0; kk < 8; kk++) {
        int src = srcbase + kk;
        float u0 = __shfl_sync(0xffffffffu, T0, src);
        float u1 = __shfl_sync(0xffffffffu, T1, src);
        float u2 = __shfl_sync(0xffffffffu, T2, src);
        float u3 = __shfl_sync(0xffffffffu, T3, src);
        float4 w0 = *(const float4*)&sw[(4 * kk) * 32 + r4];
        float4 w1 = *(const float4*)&sw[(4 * kk + 1) * 32 + r4];
        float4 w2 = *(const float4*)&sw[(4 * kk + 2) * 32 + r4];
        float4 w3 = *(const float4*)&sw[(4 * kk + 3) * 32 + r4];
        o.x = fmaf(u0, w0.x, o.x); o.y = fmaf(u0, w0.y, o.y);
        o.z = fmaf(u0, w0.z, o.z); o.w = fmaf(u0, w0.w, o.w);
        o.x = fmaf(u1, w1.x, o.x); o.y = fmaf(u1, w1.y, o.y);
        o.z = fmaf(u1, w1.z, o.z); o.w = fmaf(u1, w1.w, o.w);
        o.x = fmaf(u2, w2.x, o.x); o.y = fmaf(u2, w2.y, o.y);
        o.z = fmaf(u2, w2.z, o.z); o.w = fmaf(u2, w2.w, o.w);
        o.x = fmaf(u3, w3.x, o.x); o.y = fmaf(u3, w3.y, o.y);
        o.z = fmaf(u3, w3.z, o.z); o.w = fmaf(u3, w3.w, o.w);
    }
    return o;
}

#define NCHUNK (NN / 4)  // 25000
#define GSB 592          // 148 SM x 4 blocks: exactly one resident wave

// ------------------------------------------------------------------
// fused tail: gmlp1 | gridbar | gmlp2 | gridbar | head
// ------------------------------------------------------------------
__global__ void __launch_bounds__(256, 4) tail_kernel(
    const float* __restrict__ b1a, const float* __restrict__ w2a,
    const float* __restrict__ b2a,
    const float* __restrict__ w1b, const float* __restrict__ b1b,
    const float* __restrict__ w2b, const float* __restrict__ b2b,
    const float* __restrict__ bn1g, const float* __restrict__ bn1b,
    const float* __restrict__ fc1w, const float* __restrict__ fc1b,
    const float* __restrict__ fc2w, const float* __restrict__ fc2b,
    const float* __restrict__ bn2g, const float* __restrict__ bn2b,
    float* __restrict__ out) {
    __shared__ __align__(16) float s_w2a[1024];           // nn1_w2
    __shared__ __align__(16) float s_w1b[1024], s_w2b[1024];  // nn2
    __shared__ __align__(16) float s_fc1[1024];
    __shared__ float s_fc2[32 * 41];
    __shared__ __align__(16) float s_b1a[32], s_b2a[32];
    __shared__ __align__(16) float s_b1b[32], s_b2b[32];
    __shared__ __align__(16) float s_fc1b[32];
    __shared__ float s_fc2b[48];
    __shared__ float s_red[2][8][32];

    const int tid = threadIdx.x;
    for (int i = tid; i < 1024; i += 256) {
        s_w2a[i] = w2a[i];
        s_w1b[i] = w1b[i];
        s_w2b[i] = w2b[i];
        s_fc1[i] = fc1w[i];
    }
    for (int i = tid; i < 32 * 41; i += 256) s_fc2[i] = fc2w[i];
    if (tid < 32) {
        s_b1a[tid] = b1a[tid];
        s_b2a[tid] = b2a[tid];
        s_b1b[tid] = b1b[tid];
        s_b2b[tid] = b2b[tid];
        s_fc1b[tid] = fc1b[tid];
    }
    if (tid < 41) s_fc2b[tid] = fc2b[tid];
    if (tid >= 41 && tid < 48) s_fc2b[tid] = 0.f;
    __syncthreads();

    const int w = tid >> 5, lane = tid & 31;
    const int q = lane >> 3, r = lane & 7, r4 = r * 4;
    const int srcbase = lane & 24;

    // ================= phase 1: gmlp1 =================
    {
        float4 b1v = *(const float4*)&s_b1a[r4];
        float4 ssum = make_float4(0.f, 0.f, 0.f, 0.f), ssq = ssum;

        for (int c = blockIdx.x * 8 + w; c < NCHUNK; c += GSB * 8) {
            const int v = c * 4 + q;
            const int cnt = g_cnt[v];
            int mc = cnt;
            mc = max(mc, __shfl_xor_sync(0xffffffffu, mc, 8));
            mc = max(mc, __shfl_xor_sync(0xffffffffu, mc, 16));

            float4 a = gather_row4h(g_yh, v, r4, cnt, mc);
            float t0 = fmaxf(a.x + b1v.x, 0.f);
            float t1 = fmaxf(a.y + b1v.y, 0.f);
            float t2 = fmaxf(a.z + b1v.z, 0.f);
            float t3 = fmaxf(a.w + b1v.w, 0.f);

            float4 o = mm32(t0, t1, t2, t3, s_w2a, s_b2a, srcbase, r4);
            st_h4(&g_h1h[(size_t)v * 32 + r4], o);
            ssum = f4add(ssum, o);
            ssq.x = fmaf(o.x, o.x, ssq.x);
            ssq.y = fmaf(o.y, o.y, ssq.y);
            ssq.z = fmaf(o.z, o.z, ssq.z);
            ssq.w = fmaf(o.w, o.w, ssq.w);
        }

#pragma unroll
        for (int m = 8; m <= 16; m <<= 1) {
            ssum.x += __shfl_xor_sync(0xffffffffu, ssum.x, m);
            ssum.y += __shfl_xor_sync(0xffffffffu, ssum.y, m);
            ssum.z += __shfl_xor_sync(0xffffffffu, ssum.z, m);
            ssum.w += __shfl_xor_sync(0xffffffffu, ssum.w, m);
            ssq.x += __shfl_xor_sync(0xffffffffu, ssq.x, m);
            ssq.y += __shfl_xor_sync(0xffffffffu, ssq.y, m);
            ssq.z += __shfl_xor_sync(0xffffffffu, ssq.z, m);
            ssq.w += __shfl_xor_sync(0xffffffffu, ssq.w, m);
        }
        if (lane < 8) {
            *(float4*)&s_red[0][w][r4] = ssum;
            *(float4*)&s_red[1][w][r4] = ssq;
        }
        __syncthreads();
        if (tid < 32) {
            float s = 0.f, qq = 0.f;
#pragma unroll
            for (int ww = 0; ww < 8; ww++) {
                s += s_red[0][ww][tid];
                qq += s_red[1][ww][tid];
            }
            atomicAdd(&g_sum1[tid], s);
            atomicAdd(&g_sq1[tid], qq);
        }
    }

    grid_barrier(GSB);

    // ================= phase 2: gmlp2 =================
    {
        float4 gs = *(const float4*)&g_sum1[r4];
        float4 gq = *(const float4*)&g_sq1[r4];
        float4 sc4, sh4;
        {
            float m0 = gs.x / NN, m1 = gs.y / NN, m2 = gs.z / NN,
                  m3 = gs.w / NN;
            sc4.x = bn1g[r4] * rsqrtf(fmaxf(gq.x / NN - m0 * m0, 0.f) + 1e-5f);
            sc4.y = bn1g[r4 + 1] *
                    rsqrtf(fmaxf(gq.y / NN - m1 * m1, 0.f) + 1e-5f);
            sc4.z = bn1g[r4 + 2] *
                    rsqrtf(fmaxf(gq.z / NN - m2 * m2, 0.f) + 1e-5f);
            sc4.w = bn1g[r4 + 3] *
                    rsqrtf(fmaxf(gq.w / NN - m3 * m3, 0.f) + 1e-5f);
            sh4.x = bn1b[r4] - m0 * sc4.x;
            sh4.y = bn1b[r4 + 1] - m1 * sc4.y;
            sh4.z = bn1b[r4 + 2] - m2 * sc4.z;
            sh4.w = bn1b[r4 + 3] - m3 * sc4.w;
        }

        float4 ssum = make_float4(0.f, 0.f, 0.f, 0.f), ssq = ssum;

        for (int c = blockIdx.x * 8 + w; c < NCHUNK; c += GSB * 8) {
            const int v = c * 4 + q;
            const int cnt = g_cnt[v];
            int mc = cnt;
            mc = max(mc, __shfl_xor_sync(0xffffffffu, mc, 8));
            mc = max(mc, __shfl_xor_sync(0xffffffffu, mc, 16));

            float4 a = gather_row4h(g_h1h, v, r4, cnt, mc);
            float degp1 = (float)(cnt + 1);
            float m0 = fmaf(sc4.x, a.x, degp1 * sh4.x);
            float m1 = fmaf(sc4.y, a.y, degp1 * sh4.y);
            float m2 = fmaf(sc4.z, a.z, degp1 * sh4.z);
            float m3 = fmaf(sc4.w, a.w, degp1 * sh4.w);

            float4 t = mm32(m0, m1, m2, m3, s_w1b, s_b1b, srcbase, r4);
            t.x = fmaxf(t.x, 0.f);
            t.y = fmaxf(t.y, 0.f);
            t.z = fmaxf(t.z, 0.f);
            t.w = fmaxf(t.w, 0.f);

            float4 o = mm32(t.x, t.y, t.z, t.w, s_w2b, s_b2b, srcbase, r4);
            *(float4*)&g_h2[(size_t)v * 32 + r4] = o;
            ssum = f4add(ssum, o);
            ssq.x = fmaf(o.x, o.x, ssq.x);
            ssq.y = fmaf(o.y, o.y, ssq.y);
            ssq.z = fmaf(o.z, o.z, ssq.z);
            ssq.w = fmaf(o.w, o.w, ssq.w);
        }

#pragma unroll
        for (int m = 8; m <= 16; m <<= 1) {
            ssum.x += __shfl_xor_sync(0xffffffffu, ssum.x, m);
            ssum.y += __shfl_xor_sync(0xffffffffu, ssum.y, m);
            ssum.z += __shfl_xor_sync(0xffffffffu, ssum.z, m);
            ssum.w += __shfl_xor_sync(0xffffffffu, ssum.w, m);
            ssq.x += __shfl_xor_sync(0xffffffffu, ssq.x, m);
            ssq.y += __shfl_xor_sync(0xffffffffu, ssq.y, m);
            ssq.z += __shfl_xor_sync(0xffffffffu, ssq.z, m);
            ssq.w += __shfl_xor_sync(0xffffffffu, ssq.w, m);
        }
        __syncthreads();  // s_red reuse from phase 1
        if (lane < 8) {
            *(float4*)&s_red[0][w][r4] = ssum;
            *(float4*)&s_red[1][w][r4] = ssq;
        }
        __syncthreads();
        if (tid < 32) {
            float s = 0.f, qq = 0.f;
#pragma unroll
            for (int ww = 0; ww < 8; ww++) {
                s += s_red[0][ww][tid];
                qq += s_red[1][ww][tid];
            }
            atomicAdd(&g_sum2[tid], s);
            atomicAdd(&g_sq2[tid], qq);
        }
    }

    grid_barrier(GSB);

    // ================= phase 3: head =================
    {
        float4 gs = *(const float4*)&g_sum2[r4];
        float4 gq = *(const float4*)&g_sq2[r4];
        float4 sc4, sh4;
        {
            float m0 = gs.x / NN, m1 = gs.y / NN, m2 = gs.z / NN,
                  m3 = gs.w / NN;
            sc4.x = bn2g[r4] * rsqrtf(fmaxf(gq.x / NN - m0 * m0, 0.f) + 1e-5f);
            sc4.y = bn2g[r4 + 1] *
                    rsqrtf(fmaxf(gq.y / NN - m1 * m1, 0.f) + 1e-5f);
            sc4.z = bn2g[r4 + 2] *
                    rsqrtf(fmaxf(gq.z / NN - m2 * m2, 0.f) + 1e-5f);
            sc4.w = bn2g[r4 + 3] *
                    rsqrtf(fmaxf(gq.w / NN - m3 * m3, 0.f) + 1e-5f);
            sh4.x = bn2b[r4] - m0 * sc4.x;
            sh4.y = bn2b[r4 + 1] - m1 * sc4.y;
            sh4.z = bn2b[r4 + 2] - m2 * sc4.z;
            sh4.w = bn2b[r4 + 3] - m3 * sc4.w;
        }

        const int c0 = r * 6;
        const int nc = max(0, min(6, 41 - c0));

        for (int c = blockIdx.x * 8 + w; c < NCHUNK; c += GSB * 8) {
            const int v = c * 4 + q;
            if (r == 0) g_cnt[v] = 0;  // reset for next graph replay
            float4 h = *(const float4*)&g_h2[(size_t)v * 32 + r4];
            float x0 = fmaf(sc4.x, h.x, sh4.x);
            float x1 = fmaf(sc4.y, h.y, sh4.y);
            float x2 = fmaf(sc4.z, h.z, sh4.z);
            float x3 = fmaf(sc4.w, h.w, sh4.w);

            float4 t = mm32(x0, x1, x2, x3, s_fc1, s_fc1b, srcbase, r4);
            t.x = fmaxf(t.x, 0.f);
            t.y = fmaxf(t.y, 0.f);
            t.z = fmaxf(t.z, 0.f);
            t.w = fmaxf(t.w, 0.f);

            float o[6];
#pragma unroll
            for (int jj = 0; jj < 6; jj++) o[jj] = s_fc2b[c0 + jj];

#pragma unroll
            for (int kk = 0; kk < 8; kk++) {
                int src = srcbase + kk;
                float u0 = __shfl_sync(0xffffffffu, t.x, src);
                float u1 = __shfl_sync(0xffffffffu, t.y, src);
                float u2 = __shfl_sync(0xffffffffu, t.z, src);
                float u3 = __shfl_sync(0xffffffffu, t.w, src);
                const float* w0 = &s_fc2[(4 * kk) * 41 + c0];
                const float* w1 = &s_fc2[(4 * kk + 1) * 41 + c0];
                const float* w2r = &s_fc2[(4 * kk + 2) * 41 + c0];
                const float* w3 = &s_fc2[(4 * kk + 3) * 41 + c0];
#pragma unroll
                for (int jj = 0; jj < 6; jj++) {
                    if (jj < nc) {
                        o[jj] = fmaf(u0, w0[jj], o[jj]);
                        o[jj] = fmaf(u1, w1[jj], o[jj]);
                        o[jj] = fmaf(u2, w2r[jj], o[jj]);
                        o[jj] = fmaf(u3, w3[jj], o[jj]);
                    }
                }
            }
#pragma unroll
            for (int jj = 0; jj < 6; jj++)
                if (jj < nc) out[(size_t)v * 41 + c0 + jj] = o[jj];
        }
    }
}

// ------------------------------------------------------------------
// launch: 4 kernels; fused tail is ncu slot #4
// ------------------------------------------------------------------
static cudaStream_t g_side = nullptr;
static cudaEvent_t g_evFork = nullptr, g_evJoin = nullptr;

extern "C" void kernel_launch(void* const* d_in, const int* in_sizes, int n_in,
                              void* d_out, int out_size) {
    const float* x = (const float*)d_in[0];
    const int* ei = (const int*)d_in[1];
    const float* lin1_w = (const float*)d_in[2];
    const float* lin1_b = (const float*)d_in[3];
    const float* nn1_w1 = (const float*)d_in[4];
    const float* nn1_b1 = (const float*)d_in[5];
    const float* nn1_w2 = (const float*)d_in[6];
    const float* nn1_b2 = (const float*)d_in[7];
    const float* bn1_g = (const float*)d_in[8];
    const float* bn1_b = (const float*)d_in[9];
    const float* nn2_w1 = (const float*)d_in[10];
    const float* nn2_b1 = (const float*)d_in[11];
    const float* nn2_w2 = (const float*)d_in[12];
    const float* nn2_b2 = (const float*)d_in[13];
    const float* bn2_g = (const float*)d_in[14];
    const float* bn2_b = (const float*)d_in[15];
    const float* fc1_w = (const float*)d_in[16];
    const float* fc1_b = (const float*)d_in[17];
    const float* fc2_w = (const float*)d_in[18];
    const float* fc2_b = (const float*)d_in[19];
    float* out = (float*)d_out;

    if (!g_side) {
        int lo, hi;
        cudaDeviceGetStreamPriorityRange(&lo, &hi);
        cudaStreamCreateWithPriority(&g_side, cudaStreamNonBlocking, hi);
        cudaEventCreateWithFlags(&g_evFork, cudaEventDisableTiming);
        cudaEventCreateWithFlags(&g_evJoin, cudaEventDisableTiming);
        cudaFuncSetAttribute(gemm_kernel,
                             cudaFuncAttributeMaxDynamicSharedMemorySize,
                             GEMM_SMEM);
    }

    cudaEventRecord(g_evFork, 0);
    cudaStreamWaitEvent(g_side, g_evFork, 0);

    place2_kernel<<<256, 256, 0, g_side>>>(ei);                       // #1
    cudaEventRecord(g_evJoin, g_side);

    wc_kernel<<<(FF + 7) / 8, 256>>>(lin1_w, nn1_w1, lin1_b);         // #2
    gemm_kernel<<<(NN + BM - 1) / BM, 256, GEMM_SMEM>>>(x);           // #3

    cudaStreamWaitEvent(0, g_evJoin, 0);

    tail_kernel<<<GSB, 256>>>(nn1_b1, nn1_w2, nn1_b2,                 // #4
                              nn2_w1, nn2_b1, nn2_w2, nn2_b2,
                              bn1_g, bn1_b, fc1_w, fc1_b, fc2_w, fc2_b,
                              bn2_g, bn2_b, out);
}